// round 7
// baseline (speedup 1.0000x reference)
#include <cuda_runtime.h>

// ============================================================================
// ElementwiseTensorProducts — fused fp32 kernel, packed f32x2 FMA (FFMA2).
//
// All GEMM stages use fma.rn.f32x2 with K-parity packing:
//   - A operand pairs {A[t][k],A[t][k+1]} come free from float4 (LDS.128) loads
//   - W is staged k-pair-interleaved in smem: sW2[(k>>1)*264 + j*2 + (k&1)]
//     so {W[j][k],W[j][k+1]} is also a natural 64-bit register pair
//   - accumulators hold {even-k partial, odd-k partial}; folded at epilogue
// -> 2 MACs per fma-pipe issue, zero packing instructions.
//
// Block = 256 threads = 8 warps, tile = 64 tokens (warp w -> tokens 8w..8w+7,
// lane l -> output channels 4l..4l+3). All intermediates live in smem.
// ============================================================================

#define THREADS 256
#define TTILE   64
#define RS      264          // floats per k-pair row of interleaved weights (16B-aligned)

// smem layout (floats)
#define OFF_A   0            // 8192  : z0 tile / z1_i tile / z0_o / q tile
#define OFF_P0  8192         // 8192  : proj0 result [64][128]
#define OFF_P1  16384        // 24576 : proj1 result [64][384]
#define OFF_W   40960        // 16896 : interleaved weight buffer (64 pair-rows x 264)
#define SMEM_FLOATS 57856    // 231424 bytes

__device__ __forceinline__ unsigned long long ffma2(unsigned long long a,
                                                    unsigned long long b,
                                                    unsigned long long c) {
    unsigned long long d;
    asm("fma.rn.f32x2 %0, %1, %2, %3;" : "=l"(d) : "l"(a), "l"(b), "l"(c));
    return d;
}

__device__ __forceinline__ float fold(unsigned long long p) {
    float lo, hi;
    asm("mov.b64 {%0, %1}, %2;" : "=f"(lo), "=f"(hi) : "l"(p));
    return lo + hi;
}

// acc[tt][m] (+)= pairs over k of A[t][k] * W[j][k], j = lane*4+m.
// sA reads are warp-uniform broadcasts; sW2 reads are consecutive -> no conflicts.
__device__ __forceinline__ void gemm_tile2(const float* __restrict__ sA, int lda,
                                           const float* __restrict__ sW2, int K,
                                           unsigned long long (&acc)[8][4],
                                           int t0, int lane) {
#pragma unroll 2
    for (int k = 0; k < K; k += 4) {
        ulonglong2 a[8];
#pragma unroll
        for (int tt = 0; tt < 8; ++tt)
            a[tt] = *(const ulonglong2*)&sA[(t0 + tt) * lda + k];
        const float* wr = &sW2[(k >> 1) * RS + lane * 8];
        ulonglong2 w00 = *(const ulonglong2*)(wr);         // k,k+1 : channels j0,j1
        ulonglong2 w01 = *(const ulonglong2*)(wr + 4);     // k,k+1 : channels j2,j3
        ulonglong2 w10 = *(const ulonglong2*)(wr + RS);    // k+2,k+3 : j0,j1
        ulonglong2 w11 = *(const ulonglong2*)(wr + RS + 4);// k+2,k+3 : j2,j3
#pragma unroll
        for (int tt = 0; tt < 8; ++tt) {
            acc[tt][0] = ffma2(a[tt].x, w00.x, acc[tt][0]);
            acc[tt][1] = ffma2(a[tt].x, w00.y, acc[tt][1]);
            acc[tt][2] = ffma2(a[tt].x, w01.x, acc[tt][2]);
            acc[tt][3] = ffma2(a[tt].x, w01.y, acc[tt][3]);
        }
#pragma unroll
        for (int tt = 0; tt < 8; ++tt) {
            acc[tt][0] = ffma2(a[tt].y, w10.x, acc[tt][0]);
            acc[tt][1] = ffma2(a[tt].y, w10.y, acc[tt][1]);
            acc[tt][2] = ffma2(a[tt].y, w11.x, acc[tt][2]);
            acc[tt][3] = ffma2(a[tt].y, w11.y, acc[tt][3]);
        }
    }
}

// Load W[j][0:128] (row-major) k-pair-interleaved into sW2 at channel offset jofs
__device__ __forceinline__ void load_wt2_128(const float* __restrict__ g, float* sW2,
                                             int J, int jofs, int tid) {
    for (int e = tid; e < J * 128; e += THREADS) {
        int j = e >> 7, k = e & 127;
        sW2[(k >> 1) * RS + (jofs + j) * 2 + (k & 1)] = g[e];
    }
}

__global__ __launch_bounds__(THREADS, 1)
void etp_kernel(const float* __restrict__ z0, const float* __restrict__ z1,
                const float* __restrict__ W0l, const float* __restrict__ b0l,
                const float* __restrict__ W0r, const float* __restrict__ b0r,
                const float* __restrict__ W1l, const float* __restrict__ W1r,
                const float* __restrict__ W0o, const float* __restrict__ b0o,
                const float* __restrict__ W1o,
                float* __restrict__ out0, float* __restrict__ out1) {
    extern __shared__ float sm[];
    float* sA  = sm + OFF_A;
    float* sP0 = sm + OFF_P0;
    float* sP1 = sm + OFF_P1;
    float* sW  = sm + OFF_W;

    const int tid  = threadIdx.x;
    const int lane = tid & 31;
    const int warp = tid >> 5;
    const int t0   = warp * 8;
    const long tokbase = (long)blockIdx.x * TTILE;

    // ---- stage z0 tile + proj0 weights ----
    {
        const float4* src = (const float4*)(z0 + tokbase * 128);
        float4* dst = (float4*)sA;
        for (int e = tid; e < TTILE * 128 / 4; e += THREADS) dst[e] = src[e];
    }
    load_wt2_128(W0l, sW, 64, 0, tid);
    load_wt2_128(W0r, sW, 64, 64, tid);
    __syncthreads();

    // ---- proj0 ----
    {
        unsigned long long acc[8][4];
#pragma unroll
        for (int tt = 0; tt < 8; ++tt)
#pragma unroll
            for (int m = 0; m < 4; ++m) acc[tt][m] = 0ull;
        gemm_tile2(sA, 128, sW, 128, acc, t0, lane);
        float4 bv = (lane < 16) ? *(const float4*)&b0l[lane * 4]
                                : *(const float4*)&b0r[lane * 4 - 64];
#pragma unroll
        for (int tt = 0; tt < 8; ++tt)
            *(float4*)&sP0[(t0 + tt) * 128 + lane * 4] =
                make_float4(fold(acc[tt][0]) + bv.x, fold(acc[tt][1]) + bv.y,
                            fold(acc[tt][2]) + bv.z, fold(acc[tt][3]) + bv.w);
    }
    __syncthreads();

    // ---- proj1 (i = 0..2, weights stay resident) ----
    load_wt2_128(W1l, sW, 64, 0, tid);
    load_wt2_128(W1r, sW, 64, 64, tid);
    for (int i = 0; i < 3; ++i) {
        // stage z1[:, i, :] tile (token row stride 384 floats)
        for (int e = tid; e < 2048; e += THREADS) {
            int t = e >> 5, q = e & 31;
            ((float4*)sA)[e] =
                *(const float4*)(z1 + (tokbase + t) * 384 + i * 128 + q * 4);
        }
        __syncthreads();   // z1 tile + (first iter) W1lr ready; prior sA readers done
        unsigned long long acc[8][4];
#pragma unroll
        for (int tt = 0; tt < 8; ++tt)
#pragma unroll
            for (int m = 0; m < 4; ++m) acc[tt][m] = 0ull;
        gemm_tile2(sA, 128, sW, 128, acc, t0, lane);
#pragma unroll
        for (int tt = 0; tt < 8; ++tt)
            *(float4*)&sP1[(t0 + tt) * 384 + i * 128 + lane * 4] =
                make_float4(fold(acc[tt][0]), fold(acc[tt][1]),
                            fold(acc[tt][2]), fold(acc[tt][3]));
        __syncthreads();   // allow sA reuse next i / next phase
    }

    // ---- build z0_o = [p00 | p110] into sA; stage W0o ----
    for (int e = tid; e < 8192; e += THREADS) {
        int t = e >> 7, k = e & 127;
        float v;
        const float* p = &sP1[t * 384];
        if (k < 64) {
            v = sP0[t * 128 + k] * sP0[t * 128 + 64 + k];
        } else {
            int r = k - 64;
            v = p[r] * p[64 + r] + p[128 + r] * p[192 + r] + p[256 + r] * p[320 + r];
        }
        sA[e] = v;
    }
    load_wt2_128(W0o, sW, 128, 0, tid);
    __syncthreads();

    // ---- out0 ----
    {
        unsigned long long acc[8][4];
#pragma unroll
        for (int tt = 0; tt < 8; ++tt)
#pragma unroll
            for (int m = 0; m < 4; ++m) acc[tt][m] = 0ull;
        gemm_tile2(sA, 128, sW, 128, acc, t0, lane);
        float4 bv = *(const float4*)&b0o[lane * 4];
#pragma unroll
        for (int tt = 0; tt < 8; ++tt)
            *(float4*)&out0[(tokbase + t0 + tt) * 128 + lane * 4] =
                make_float4(fold(acc[tt][0]) + bv.x, fold(acc[tt][1]) + bv.y,
                            fold(acc[tt][2]) + bv.z, fold(acc[tt][3]) + bv.w);
    }

    // ---- out1: K=192 GEMM. i (irrep) outer, K chunked 3x64 (ch inner) so only
    //      one packed acc tile (64 regs) is live at a time. W1o chunk restaged
    //      per (i,ch): cheap L2 reads vs. 2x accumulator registers. ----
    for (int i = 0; i < 3; ++i) {            // runtime loop (code-size control)
        unsigned long long acc[8][4];
#pragma unroll
        for (int tt = 0; tt < 8; ++tt)
#pragma unroll
            for (int m = 0; m < 4; ++m) acc[tt][m] = 0ull;

#pragma unroll
        for (int ch = 0; ch < 3; ++ch) {     // unrolled: q-build specializes on ch
            __syncthreads();                 // prior sA / sW readers done
            // stage W1o[:, ch*64 : ch*64+64] k-pair-interleaved
            for (int e = tid; e < 128 * 64; e += THREADS) {
                int c = e >> 6, kk = e & 63;
                sW[(kk >> 1) * RS + c * 2 + (kk & 1)] = W1o[c * 192 + ch * 64 + kk];
            }
            // build q_chunk tile [64 tok][64 r] into sA
            for (int e = tid; e < 4096; e += THREADS) {
                int t = e >> 6, r = e & 63;
                const float* p = &sP1[t * 384];
                float v;
                if (ch == 0) {
                    v = sP0[t * 128 + r] * p[i * 128 + 64 + r];            // q011
                } else if (ch == 1) {
                    v = p[i * 128 + r] * sP0[t * 128 + 64 + r];            // q101
                } else {
                    int i1 = (i + 1 < 3) ? i + 1 : i - 2;
                    int i2 = (i + 2 < 3) ? i + 2 : i - 1;
                    v = p[i1 * 128 + r] * p[i2 * 128 + 64 + r]
                      - p[i2 * 128 + r] * p[i1 * 128 + 64 + r];            // q111
                }
                sA[e] = v;
            }
            __syncthreads();                 // q tile + W chunk ready
            gemm_tile2(sA, 64, sW, 64, acc, t0, lane);
        }

        // fold + write out1 (B,N,3,C): token*384 + i*128 + c
#pragma unroll
        for (int tt = 0; tt < 8; ++tt)
            *(float4*)&out1[(tokbase + t0 + tt) * 384 + i * 128 + lane * 4] =
                make_float4(fold(acc[tt][0]), fold(acc[tt][1]),
                            fold(acc[tt][2]), fold(acc[tt][3]));
    }
}

extern "C" void kernel_launch(void* const* d_in, const int* in_sizes, int n_in,
                              void* d_out, int out_size) {
    const float* z0  = (const float*)d_in[0];
    const float* z1  = (const float*)d_in[1];
    const float* W0l = (const float*)d_in[2];
    const float* b0l = (const float*)d_in[3];
    const float* W0r = (const float*)d_in[4];
    const float* b0r = (const float*)d_in[5];
    const float* W1l = (const float*)d_in[6];
    const float* W1r = (const float*)d_in[7];
    const float* W0o = (const float*)d_in[8];
    const float* b0o = (const float*)d_in[9];
    const float* W1o = (const float*)d_in[10];

    const int BN = in_sizes[0] / 128;            // 65536 tokens
    float* out0 = (float*)d_out;
    float* out1 = (float*)d_out + (long)BN * 128;

    const int smem_bytes = SMEM_FLOATS * sizeof(float);   // 231424
    cudaFuncSetAttribute(etp_kernel, cudaFuncAttributeMaxDynamicSharedMemorySize,
                         smem_bytes);

    dim3 grid(BN / TTILE);   // 1024
    dim3 block(THREADS);
    etp_kernel<<<grid, block, smem_bytes>>>(z0, z1, W0l, b0l, W0r, b0r,
                                            W1l, W1r, W0o, b0o, W1o,
                                            out0, out1);
}

// round 9
// speedup vs baseline: 1.1146x; 1.1146x over previous
#include <cuda_runtime.h>
#include <cstdint>

// ============================================================================
// ElementwiseTensorProducts — fused kernel on tensor cores via
// mma.sync.m16n8k8 tf32 with 3xTF32 precision splitting (fp32-class accuracy).
//
// Per block: 64 tokens. Every GEMM stage streams K in 32-wide chunks:
//   stage A-chunk hi/lo [64][36] + W-chunk hi/lo transposed [32][136] in smem,
//   then each warp runs 4 k-steps x 8 n-tiles x 3 split-MMAs.
// Warp grid: 8 warps = 4 m16-tiles x 2 n-halves (64 channels each).
// Intermediates (P0, P1) live in smem; q/p tiles built elementwise from them.
// ============================================================================

#define THREADS 256
#define SA  36     // A tile row stride (frag LDS bank = 4*grp+qd : conflict-free)
#define SW  136    // W tile row stride (frag LDS bank = 8*qd+grp : conflict-free)
#define SP0 136
#define SP1 392

// smem float offsets
#define OFF_AHI 0          // 64*36  = 2304
#define OFF_ALO 2304
#define OFF_WHI 4608       // 32*136 = 4352
#define OFF_WLO 8960
#define OFF_P0  13312      // 64*136 = 8704
#define OFF_P1  22016      // 64*392 = 25088
#define SMEM_FLOATS 47104  // 188,416 bytes

__device__ __forceinline__ void split2(float v, uint32_t& hb, uint32_t& lb) {
    asm("cvt.rna.tf32.f32 %0, %1;" : "=r"(hb) : "f"(v));
    float lo = v - __uint_as_float(hb);
    asm("cvt.rna.tf32.f32 %0, %1;" : "=r"(lb) : "f"(lo));
}

__device__ __forceinline__ void mma8(float (&c)[4], const uint32_t (&a)[4],
                                     const uint32_t b0, const uint32_t b1) {
    asm volatile(
        "mma.sync.aligned.m16n8k8.row.col.f32.tf32.tf32.f32 "
        "{%0,%1,%2,%3}, {%4,%5,%6,%7}, {%8,%9}, {%0,%1,%2,%3};"
        : "+f"(c[0]), "+f"(c[1]), "+f"(c[2]), "+f"(c[3])
        : "r"(a[0]), "r"(a[1]), "r"(a[2]), "r"(a[3]), "r"(b0), "r"(b1));
}

// One staged 32-k chunk: acc[nt] += A(16xk32) * W(k32 x n64-half), 3 splits.
__device__ __forceinline__ void gemm_chunk(float (&acc)[8][4],
        const float* __restrict__ aH, const float* __restrict__ aL,
        const float* __restrict__ wH, const float* __restrict__ wL,
        int mrow0, int nb, int lane) {
    const int grp = lane >> 2, qd = lane & 3;
    const float* pAh = aH + (mrow0 + grp) * SA + qd;
    const float* pAl = aL + (mrow0 + grp) * SA + qd;
#pragma unroll
    for (int ks = 0; ks < 4; ++ks) {
        uint32_t ah[4], al[4];
        ah[0] = __float_as_uint(pAh[ks * 8]);
        ah[1] = __float_as_uint(pAh[8 * SA + ks * 8]);
        ah[2] = __float_as_uint(pAh[ks * 8 + 4]);
        ah[3] = __float_as_uint(pAh[8 * SA + ks * 8 + 4]);
        al[0] = __float_as_uint(pAl[ks * 8]);
        al[1] = __float_as_uint(pAl[8 * SA + ks * 8]);
        al[2] = __float_as_uint(pAl[ks * 8 + 4]);
        al[3] = __float_as_uint(pAl[8 * SA + ks * 8 + 4]);
        const float* pWh = wH + (ks * 8 + qd) * SW + nb + grp;
        const float* pWl = wL + (ks * 8 + qd) * SW + nb + grp;
#pragma unroll
        for (int nt = 0; nt < 8; ++nt) {
            uint32_t bh0 = __float_as_uint(pWh[nt * 8]);
            uint32_t bh1 = __float_as_uint(pWh[4 * SW + nt * 8]);
            uint32_t bl0 = __float_as_uint(pWl[nt * 8]);
            uint32_t bl1 = __float_as_uint(pWl[4 * SW + nt * 8]);
            mma8(acc[nt], ah, bh0, bh1);   // hi * hi
            mma8(acc[nt], ah, bl0, bl1);   // hi * lo
            mma8(acc[nt], al, bh0, bh1);   // lo * hi
        }
    }
}

// Stage W chunk transposed+split: rows 0-63 from Wa, 64-127 from Wb (row-major,
// leading dim ld). Warp-uniform branch (j blocks of 8). STS conflict-free.
__device__ __forceinline__ void stage_W(const float* __restrict__ Wa,
                                        const float* __restrict__ Wb,
                                        int ld, int kb,
                                        float* __restrict__ wH,
                                        float* __restrict__ wL, int tid) {
#pragma unroll
    for (int it = 0; it < 16; ++it) {
        int e = tid + it * THREADS;              // 0..4095
        int kk = (e & 3) | ((e >> 9) << 2);      // 0..31
        int j  = (e >> 2) & 127;                 // 0..127
        const float* src = (j < 64) ? (Wa + j * ld) : (Wb + (j - 64) * ld);
        float v = src[kb + kk];
        uint32_t hb, lb; split2(v, hb, lb);
        wH[kk * SW + j] = __uint_as_float(hb);
        wL[kk * SW + j] = __uint_as_float(lb);
    }
}

// Stage A chunk from gmem: 64 tokens x 32 cols (src pre-offset to chunk).
__device__ __forceinline__ void stage_A_g(const float* __restrict__ src, int ld,
                                          float* __restrict__ aH,
                                          float* __restrict__ aL, int tid) {
#pragma unroll
    for (int it = 0; it < 8; ++it) {
        int e = tid + it * THREADS;              // 0..2047
        int c = (e & 3) | ((e >> 8) << 2);       // 0..31
        int t = (e >> 2) & 63;
        float v = src[(long)t * ld + c];
        uint32_t hb, lb; split2(v, hb, lb);
        aH[t * SA + c] = __uint_as_float(hb);
        aL[t * SA + c] = __uint_as_float(lb);
    }
}

#define ZERO_ACC(acc) do {                                   \
    _Pragma("unroll") for (int _n = 0; _n < 8; ++_n)         \
    _Pragma("unroll") for (int _m = 0; _m < 4; ++_m)         \
        (acc)[_n][_m] = 0.f;                                 \
} while (0)

__global__ __launch_bounds__(THREADS, 1)
void etp_mma_kernel(const float* __restrict__ z0, const float* __restrict__ z1,
                    const float* __restrict__ W0l, const float* __restrict__ b0l,
                    const float* __restrict__ W0r, const float* __restrict__ b0r,
                    const float* __restrict__ W1l, const float* __restrict__ W1r,
                    const float* __restrict__ W0o, const float* __restrict__ b0o,
                    const float* __restrict__ W1o,
                    float* __restrict__ out0, float* __restrict__ out1) {
    extern __shared__ float sm[];
    float* aH  = sm + OFF_AHI;
    float* aL  = sm + OFF_ALO;
    float* wH  = sm + OFF_WHI;
    float* wL  = sm + OFF_WLO;
    float* sP0 = sm + OFF_P0;
    float* sP1 = sm + OFF_P1;

    const int tid  = threadIdx.x;
    const int lane = tid & 31;
    const int warp = tid >> 5;
    const int grp  = lane >> 2, qd = lane & 3;
    const int mrow0 = (warp & 3) * 16;           // warp's 16-token row block
    const int nb    = (warp >> 2) * 64;          // warp's 64-channel half
    const long tokbase = (long)blockIdx.x * 64;

    float acc[8][4];

    // ================= proj0: P0 = z0 @ [W0l|W0r]^T + bias =================
    ZERO_ACC(acc);
    for (int c = 0; c < 4; ++c) {
        __syncthreads();
        stage_A_g(z0 + tokbase * 128 + c * 32, 128, aH, aL, tid);
        stage_W(W0l, W0r, 128, c * 32, wH, wL, tid);
        __syncthreads();
        gemm_chunk(acc, aH, aL, wH, wL, mrow0, nb, lane);
    }
#pragma unroll
    for (int nt = 0; nt < 8; ++nt) {
        int col = nb + nt * 8 + 2 * qd;
        float bx = (col < 64) ? b0l[col] : b0r[col - 64];
        float by = (col < 64) ? b0l[col + 1] : b0r[col - 63];
        *(float2*)&sP0[(mrow0 + grp) * SP0 + col] =
            make_float2(acc[nt][0] + bx, acc[nt][1] + by);
        *(float2*)&sP0[(mrow0 + grp + 8) * SP0 + col] =
            make_float2(acc[nt][2] + bx, acc[nt][3] + by);
    }

    // ================= proj1: P1_i = z1_i @ [W1l|W1r]^T =================
    for (int i = 0; i < 3; ++i) {
        ZERO_ACC(acc);
        for (int c = 0; c < 4; ++c) {
            __syncthreads();
            stage_A_g(z1 + tokbase * 384 + i * 128 + c * 32, 384, aH, aL, tid);
            stage_W(W1l, W1r, 128, c * 32, wH, wL, tid);
            __syncthreads();
            gemm_chunk(acc, aH, aL, wH, wL, mrow0, nb, lane);
        }
#pragma unroll
        for (int nt = 0; nt < 8; ++nt) {
            int col = i * 128 + nb + nt * 8 + 2 * qd;
            *(float2*)&sP1[(mrow0 + grp) * SP1 + col] =
                make_float2(acc[nt][0], acc[nt][1]);
            *(float2*)&sP1[(mrow0 + grp + 8) * SP1 + col] =
                make_float2(acc[nt][2], acc[nt][3]);
        }
    }

    // ================= out0 = [p00 | p110] @ W0o^T + b0o =================
    ZERO_ACC(acc);
    for (int c = 0; c < 4; ++c) {
        __syncthreads();
        const int cb = c * 32;
#pragma unroll
        for (int it = 0; it < 8; ++it) {
            int e = tid + it * THREADS;
            int cc = (e & 3) | ((e >> 8) << 2);
            int t  = (e >> 2) & 63;
            int k  = cb + cc;
            float v;
            if (cb < 64) {
                v = sP0[t * SP0 + k] * sP0[t * SP0 + 64 + k];
            } else {
                int r = k - 64;
                const float* p = &sP1[t * SP1];
                v = p[r] * p[64 + r] + p[128 + r] * p[192 + r]
                  + p[256 + r] * p[320 + r];
            }
            uint32_t hb, lb; split2(v, hb, lb);
            aH[t * SA + cc] = __uint_as_float(hb);
            aL[t * SA + cc] = __uint_as_float(lb);
        }
        stage_W(W0o, W0o + 64 * 128, 128, cb, wH, wL, tid);
        __syncthreads();
        gemm_chunk(acc, aH, aL, wH, wL, mrow0, nb, lane);
    }
#pragma unroll
    for (int nt = 0; nt < 8; ++nt) {
        int col = nb + nt * 8 + 2 * qd;
        float2 b = *(const float2*)&b0o[col];
        *(float2*)&out0[(tokbase + mrow0 + grp) * 128 + col] =
            make_float2(acc[nt][0] + b.x, acc[nt][1] + b.y);
        *(float2*)&out0[(tokbase + mrow0 + grp + 8) * 128 + col] =
            make_float2(acc[nt][2] + b.x, acc[nt][3] + b.y);
    }

    // ================= out1_i = [q011|q101|q111]_i @ W1o^T (K=192) ==========
    for (int i = 0; i < 3; ++i) {
        const int i1 = (i + 1 < 3) ? i + 1 : i - 2;
        const int i2 = (i + 2 < 3) ? i + 2 : i - 1;
        ZERO_ACC(acc);
        for (int ccu = 0; ccu < 6; ++ccu) {
            __syncthreads();
            const int cb = ccu * 32;
#pragma unroll
            for (int it = 0; it < 8; ++it) {
                int e = tid + it * THREADS;
                int cc = (e & 3) | ((e >> 8) << 2);
                int t  = (e >> 2) & 63;
                int k  = cb + cc;
                const float* p = &sP1[t * SP1];
                float v;
                if (cb < 64) {                       // q011 = P0l * P1r_i
                    v = sP0[t * SP0 + k] * p[i * 128 + 64 + k];
                } else if (cb < 128) {               // q101 = P1l_i * P0r
                    int r = k - 64;
                    v = p[i * 128 + r] * sP0[t * SP0 + 64 + r];
                } else {                             // q111 = cross(P1l,P1r)_i
                    int r = k - 128;
                    v = p[i1 * 128 + r] * p[i2 * 128 + 64 + r]
                      - p[i2 * 128 + r] * p[i1 * 128 + 64 + r];
                }
                uint32_t hb, lb; split2(v, hb, lb);
                aH[t * SA + cc] = __uint_as_float(hb);
                aL[t * SA + cc] = __uint_as_float(lb);
            }
            stage_W(W1o, W1o + 64 * 192, 192, cb, wH, wL, tid);
            __syncthreads();
            gemm_chunk(acc, aH, aL, wH, wL, mrow0, nb, lane);
        }
#pragma unroll
        for (int nt = 0; nt < 8; ++nt) {
            int col = nb + nt * 8 + 2 * qd;
            *(float2*)&out1[(tokbase + mrow0 + grp) * 384 + i * 128 + col] =
                make_float2(acc[nt][0], acc[nt][1]);
            *(float2*)&out1[(tokbase + mrow0 + grp + 8) * 384 + i * 128 + col] =
                make_float2(acc[nt][2], acc[nt][3]);
        }
    }
}

extern "C" void kernel_launch(void* const* d_in, const int* in_sizes, int n_in,
                              void* d_out, int out_size) {
    const float* z0  = (const float*)d_in[0];
    const float* z1  = (const float*)d_in[1];
    const float* W0l = (const float*)d_in[2];
    const float* b0l = (const float*)d_in[3];
    const float* W0r = (const float*)d_in[4];
    const float* b0r = (const float*)d_in[5];
    const float* W1l = (const float*)d_in[6];
    const float* W1r = (const float*)d_in[7];
    const float* W0o = (const float*)d_in[8];
    const float* b0o = (const float*)d_in[9];
    const float* W1o = (const float*)d_in[10];

    const int BN = in_sizes[0] / 128;            // 65536 tokens
    float* out0 = (float*)d_out;
    float* out1 = (float*)d_out + (long)BN * 128;

    const int smem_bytes = SMEM_FLOATS * sizeof(float);   // 188,416
    cudaFuncSetAttribute(etp_mma_kernel,
                         cudaFuncAttributeMaxDynamicSharedMemorySize, smem_bytes);

    dim3 grid(BN / 64);    // 1024
    dim3 block(THREADS);
    etp_mma_kernel<<<grid, block, smem_bytes>>>(z0, z1, W0l, b0l, W0r, b0r,
                                                W1l, W1r, W0o, b0o, W1o,
                                                out0, out1);
}

// round 10
// speedup vs baseline: 1.5943x; 1.4304x over previous
#include <cuda_runtime.h>
#include <cuda_bf16.h>
#include <cstdint>

// ============================================================================
// ElementwiseTensorProducts — tensor cores via mma.sync.m16n8k16 bf16 with
// 2-component bf16 splitting (hi/lo, 3 MMAs: hh+hl+lh) -> ~fp32 accuracy.
//
// Per block: 32 tokens, 256 threads (8 warps: 2 m16-tiles x 4 n32-quarters).
// 91KB smem/CTA -> 2 CTAs/SM co-resident (cross-CTA stage/MMA overlap).
// Tiles store packed bf16 k-pairs (u32): frag loads are single 32-bit LDS,
// layouts chosen bank-conflict-free; staging gmem reads are 32B-contiguous.
// K streamed in 32-wide chunks; intermediates P0/P1 in fp32 smem.
// ============================================================================

#define THREADS 256
#define TOK     32
#define SAU     20     // A tile stride (u32 pairs): frag banks 20*grp+qd distinct
#define SWN     136    // W tile stride (u32 pairs): frag banks 8*qd+grp distinct
#define SP0F    140    // P0 stride (floats): epi banks 12*grp+2qd distinct
#define SP1F    396    // P1 stride (floats)

// smem byte offsets
#define OFF_AH  0          // 32*20*4   = 2560
#define OFF_AL  2560
#define OFF_WH  5120       // 16*136*4  = 8704
#define OFF_WL  13824
#define OFF_P0  22528      // 32*140*4  = 17920
#define OFF_P1  40448      // 32*396*4  = 50688
#define SMEM_BYTES 91136

__device__ __forceinline__ uint32_t pack2(float v0, float v1) {
    __nv_bfloat162 p = __floats2bfloat162_rn(v0, v1);   // v0 -> low half
    return *(uint32_t*)&p;
}

// hi = packed bf16(v0,v1); lo = packed bf16 of residuals
__device__ __forceinline__ void split_pair(float v0, float v1,
                                           uint32_t& h, uint32_t& l) {
    h = pack2(v0, v1);
    float h0 = __uint_as_float(h << 16);
    float h1 = __uint_as_float(h & 0xffff0000u);
    l = pack2(v0 - h0, v1 - h1);
}

__device__ __forceinline__ void mma16(float (&c)[4], const uint32_t (&a)[4],
                                      uint32_t b0, uint32_t b1) {
    asm volatile(
        "mma.sync.aligned.m16n8k16.row.col.f32.bf16.bf16.f32 "
        "{%0,%1,%2,%3}, {%4,%5,%6,%7}, {%8,%9}, {%0,%1,%2,%3};"
        : "+f"(c[0]), "+f"(c[1]), "+f"(c[2]), "+f"(c[3])
        : "r"(a[0]), "r"(a[1]), "r"(a[2]), "r"(a[3]), "r"(b0), "r"(b1));
}

// One 32-k chunk: acc[nt] += A(m16 x k32) * W(k32 x n32-quarter), 3 splits.
__device__ __forceinline__ void gemm_chunk(float (&acc)[4][4],
        const uint32_t* __restrict__ aH, const uint32_t* __restrict__ aL,
        const uint32_t* __restrict__ wH, const uint32_t* __restrict__ wL,
        int mrow0, int nb, int lane) {
    const int grp = lane >> 2, qd = lane & 3;
    const uint32_t* pah = aH + (mrow0 + grp) * SAU + qd;
    const uint32_t* pal = aL + (mrow0 + grp) * SAU + qd;
#pragma unroll
    for (int ks = 0; ks < 2; ++ks) {
        uint32_t ah[4], al[4];
        ah[0] = pah[8 * ks];           ah[1] = pah[8 * SAU + 8 * ks];
        ah[2] = pah[8 * ks + 4];       ah[3] = pah[8 * SAU + 8 * ks + 4];
        al[0] = pal[8 * ks];           al[1] = pal[8 * SAU + 8 * ks];
        al[2] = pal[8 * ks + 4];       al[3] = pal[8 * SAU + 8 * ks + 4];
        const uint32_t* pwh = wH + (8 * ks + qd) * SWN + nb + grp;
        const uint32_t* pwl = wL + (8 * ks + qd) * SWN + nb + grp;
#pragma unroll
        for (int nt = 0; nt < 4; ++nt) {
            uint32_t bh0 = pwh[8 * nt], bh1 = pwh[4 * SWN + 8 * nt];
            uint32_t bl0 = pwl[8 * nt], bl1 = pwl[4 * SWN + 8 * nt];
            mma16(acc[nt], ah, bh0, bh1);   // hi*hi
            mma16(acc[nt], ah, bl0, bl1);   // hi*lo
            mma16(acc[nt], al, bh0, bh1);   // lo*hi
        }
    }
}

// Stage W chunk: rows 0-63 from Wa, 64-127 from Wb (row-major [n][ld]),
// k-pair packed. Lane map: kp_low=e&3, n_low=(e>>2)&7 -> gmem 32B rows,
// STS banks 8*kp_low + n_low : conflict-free. Branch warp-uniform.
__device__ __forceinline__ void stage_W(const float* __restrict__ Wa,
                                        const float* __restrict__ Wb,
                                        int ld, int kb,
                                        uint32_t* __restrict__ wH,
                                        uint32_t* __restrict__ wL, int tid) {
#pragma unroll
    for (int it = 0; it < 8; ++it) {
        int e  = tid + it * THREADS;                 // 0..2047
        int kp = (e & 3) | (((e >> 5) & 3) << 2);    // 0..15
        int n  = ((e >> 2) & 7) | ((e >> 7) << 3);   // 0..127
        const float* src = (n < 64) ? (Wa + n * ld) : (Wb + (n - 64) * ld);
        float2 v = *(const float2*)(src + kb + 2 * kp);
        uint32_t h, l; split_pair(v.x, v.y, h, l);
        wH[kp * SWN + n] = h;
        wL[kp * SWN + n] = l;
    }
}

// Stage A chunk from gmem: 32 tokens x 16 k-pairs.
__device__ __forceinline__ void stage_A_g(const float* __restrict__ src, int ld,
                                          uint32_t* __restrict__ aH,
                                          uint32_t* __restrict__ aL, int tid) {
#pragma unroll
    for (int it = 0; it < 2; ++it) {
        int e  = tid + it * THREADS;                 // 0..511
        int kp = (e & 3) | (((e >> 5) & 3) << 2);    // 0..15
        int t  = ((e >> 2) & 7) | ((e >> 7) << 3);   // 0..31
        float2 v = *(const float2*)(src + (long)t * ld + 2 * kp);
        uint32_t h, l; split_pair(v.x, v.y, h, l);
        aH[t * SAU + kp] = h;
        aL[t * SAU + kp] = l;
    }
}

#define ZERO_ACC(acc) do {                                   \
    _Pragma("unroll") for (int _n = 0; _n < 4; ++_n)         \
    _Pragma("unroll") for (int _m = 0; _m < 4; ++_m)         \
        (acc)[_n][_m] = 0.f;                                 \
} while (0)

__global__ __launch_bounds__(THREADS, 2)
void etp_bf16_kernel(const float* __restrict__ z0, const float* __restrict__ z1,
                     const float* __restrict__ W0l, const float* __restrict__ b0l,
                     const float* __restrict__ W0r, const float* __restrict__ b0r,
                     const float* __restrict__ W1l, const float* __restrict__ W1r,
                     const float* __restrict__ W0o, const float* __restrict__ b0o,
                     const float* __restrict__ W1o,
                     float* __restrict__ out0, float* __restrict__ out1) {
    extern __shared__ char smem[];
    uint32_t* aH  = (uint32_t*)(smem + OFF_AH);
    uint32_t* aL  = (uint32_t*)(smem + OFF_AL);
    uint32_t* wH  = (uint32_t*)(smem + OFF_WH);
    uint32_t* wL  = (uint32_t*)(smem + OFF_WL);
    float*    sP0 = (float*)(smem + OFF_P0);
    float*    sP1 = (float*)(smem + OFF_P1);

    const int tid  = threadIdx.x;
    const int lane = tid & 31;
    const int warp = tid >> 5;
    const int grp  = lane >> 2, qd = lane & 3;
    const int mrow0 = (warp & 1) * 16;          // warp's 16-token block
    const int nb    = (warp >> 1) * 32;         // warp's 32-channel quarter
    const long tokbase = (long)blockIdx.x * TOK;

    float acc[4][4];

    // ================= proj0: P0 = z0 @ [W0l|W0r]^T + bias =================
    ZERO_ACC(acc);
    for (int c = 0; c < 4; ++c) {
        __syncthreads();
        stage_A_g(z0 + tokbase * 128 + c * 32, 128, aH, aL, tid);
        stage_W(W0l, W0r, 128, c * 32, wH, wL, tid);
        __syncthreads();
        gemm_chunk(acc, aH, aL, wH, wL, mrow0, nb, lane);
    }
#pragma unroll
    for (int nt = 0; nt < 4; ++nt) {
        int col = nb + nt * 8 + 2 * qd;
        float bx = (col < 64) ? b0l[col] : b0r[col - 64];
        float by = (col < 64) ? b0l[col + 1] : b0r[col - 63];
        *(float2*)&sP0[(mrow0 + grp) * SP0F + col] =
            make_float2(acc[nt][0] + bx, acc[nt][1] + by);
        *(float2*)&sP0[(mrow0 + grp + 8) * SP0F + col] =
            make_float2(acc[nt][2] + bx, acc[nt][3] + by);
    }

    // ================= proj1: P1_i = z1_i @ [W1l|W1r]^T =================
    for (int i = 0; i < 3; ++i) {
        ZERO_ACC(acc);
        for (int c = 0; c < 4; ++c) {
            __syncthreads();
            stage_A_g(z1 + tokbase * 384 + i * 128 + c * 32, 384, aH, aL, tid);
            stage_W(W1l, W1r, 128, c * 32, wH, wL, tid);
            __syncthreads();
            gemm_chunk(acc, aH, aL, wH, wL, mrow0, nb, lane);
        }
#pragma unroll
        for (int nt = 0; nt < 4; ++nt) {
            int col = i * 128 + nb + nt * 8 + 2 * qd;
            *(float2*)&sP1[(mrow0 + grp) * SP1F + col] =
                make_float2(acc[nt][0], acc[nt][1]);
            *(float2*)&sP1[(mrow0 + grp + 8) * SP1F + col] =
                make_float2(acc[nt][2], acc[nt][3]);
        }
    }

    // ================= out0 = [p00 | p110] @ W0o^T + b0o =================
    ZERO_ACC(acc);
    for (int c = 0; c < 4; ++c) {
        __syncthreads();
        const int cb = c * 32;
#pragma unroll
        for (int it = 0; it < 2; ++it) {
            int e  = tid + it * THREADS;
            int kp = (e & 3) | (((e >> 5) & 3) << 2);
            int t  = ((e >> 2) & 7) | ((e >> 7) << 3);
            int k  = cb + 2 * kp;
            float v0, v1;
            if (cb < 64) {                            // p00 = P0l * P0r
                const float* p = &sP0[t * SP0F];
                v0 = p[k] * p[64 + k];
                v1 = p[k + 1] * p[64 + k + 1];
            } else {                                  // p110 = sum_i P1l_i*P1r_i
                int r = k - 64;
                const float* p = &sP1[t * SP1F];
                v0 = p[r] * p[64 + r] + p[128 + r] * p[192 + r]
                   + p[256 + r] * p[320 + r];
                v1 = p[r + 1] * p[65 + r] + p[129 + r] * p[193 + r]
                   + p[257 + r] * p[321 + r];
            }
            uint32_t h, l; split_pair(v0, v1, h, l);
            aH[t * SAU + kp] = h;
            aL[t * SAU + kp] = l;
        }
        stage_W(W0o, W0o + 64 * 128, 128, cb, wH, wL, tid);
        __syncthreads();
        gemm_chunk(acc, aH, aL, wH, wL, mrow0, nb, lane);
    }
#pragma unroll
    for (int nt = 0; nt < 4; ++nt) {
        int col = nb + nt * 8 + 2 * qd;
        float2 b = *(const float2*)&b0o[col];
        *(float2*)&out0[(tokbase + mrow0 + grp) * 128 + col] =
            make_float2(acc[nt][0] + b.x, acc[nt][1] + b.y);
        *(float2*)&out0[(tokbase + mrow0 + grp + 8) * 128 + col] =
            make_float2(acc[nt][2] + b.x, acc[nt][3] + b.y);
    }

    // ============ out1_i = [q011|q101|q111]_i @ W1o^T (K=192, 6 chunks) ======
    for (int i = 0; i < 3; ++i) {
        const int i1 = (i + 1 < 3) ? i + 1 : i - 2;
        const int i2 = (i + 2 < 3) ? i + 2 : i - 1;
        ZERO_ACC(acc);
        for (int cc = 0; cc < 6; ++cc) {
            __syncthreads();
            const int cb = cc * 32;
#pragma unroll
            for (int it = 0; it < 2; ++it) {
                int e  = tid + it * THREADS;
                int kp = (e & 3) | (((e >> 5) & 3) << 2);
                int t  = ((e >> 2) & 7) | ((e >> 7) << 3);
                int k  = cb + 2 * kp;
                const float* p  = &sP1[t * SP1F];
                const float* p0 = &sP0[t * SP0F];
                float v0, v1;
                if (cb < 64) {                        // q011 = P0l * P1r_i
                    v0 = p0[k] * p[i * 128 + 64 + k];
                    v1 = p0[k + 1] * p[i * 128 + 65 + k];
                } else if (cb < 128) {                // q101 = P1l_i * P0r
                    int r = k - 64;
                    v0 = p[i * 128 + r] * p0[64 + r];
                    v1 = p[i * 128 + r + 1] * p0[65 + r];
                } else {                              // q111 = cross(P1l,P1r)_i
                    int r = k - 128;
                    v0 = p[i1 * 128 + r] * p[i2 * 128 + 64 + r]
                       - p[i2 * 128 + r] * p[i1 * 128 + 64 + r];
                    v1 = p[i1 * 128 + r + 1] * p[i2 * 128 + 65 + r]
                       - p[i2 * 128 + r + 1] * p[i1 * 128 + 65 + r];
                }
                uint32_t h, l; split_pair(v0, v1, h, l);
                aH[t * SAU + kp] = h;
                aL[t * SAU + kp] = l;
            }
            stage_W(W1o, W1o + 64 * 192, 192, cb, wH, wL, tid);
            __syncthreads();
            gemm_chunk(acc, aH, aL, wH, wL, mrow0, nb, lane);
        }
#pragma unroll
        for (int nt = 0; nt < 4; ++nt) {
            int col = nb + nt * 8 + 2 * qd;
            *(float2*)&out1[(tokbase + mrow0 + grp) * 384 + i * 128 + col] =
                make_float2(acc[nt][0], acc[nt][1]);
            *(float2*)&out1[(tokbase + mrow0 + grp + 8) * 384 + i * 128 + col] =
                make_float2(acc[nt][2], acc[nt][3]);
        }
    }
}

extern "C" void kernel_launch(void* const* d_in, const int* in_sizes, int n_in,
                              void* d_out, int out_size) {
    const float* z0  = (const float*)d_in[0];
    const float* z1  = (const float*)d_in[1];
    const float* W0l = (const float*)d_in[2];
    const float* b0l = (const float*)d_in[3];
    const float* W0r = (const float*)d_in[4];
    const float* b0r = (const float*)d_in[5];
    const float* W1l = (const float*)d_in[6];
    const float* W1r = (const float*)d_in[7];
    const float* W0o = (const float*)d_in[8];
    const float* b0o = (const float*)d_in[9];
    const float* W1o = (const float*)d_in[10];

    const int BN = in_sizes[0] / 128;            // 65536 tokens
    float* out0 = (float*)d_out;
    float* out1 = (float*)d_out + (long)BN * 128;

    cudaFuncSetAttribute(etp_bf16_kernel,
                         cudaFuncAttributeMaxDynamicSharedMemorySize, SMEM_BYTES);

    dim3 grid(BN / TOK);    // 2048
    dim3 block(THREADS);
    etp_bf16_kernel<<<grid, block, SMEM_BYTES>>>(z0, z1, W0l, b0l, W0r, b0r,
                                                 W1l, W1r, W0o, b0o, W1o,
                                                 out0, out1);
}

// round 11
// speedup vs baseline: 2.6718x; 1.6759x over previous
#include <cuda_runtime.h>
#include <cuda_bf16.h>
#include <cstdint>

// ============================================================================
// ElementwiseTensorProducts — mma.sync.m16n8k16 bf16, 2-way split (hh+hl+lh).
//
// R11 changes vs R10:
//  * Weights pre-split ONCE per launch into __device__ scratch (packed bf16
//    hi/lo, already in smem tile layout) by a tiny prep kernel. Main-kernel W
//    staging = pure uint4 copy (no cvt/split ALU, 4x fewer instructions).
//  * proj1/out1 restructured: one staged W chunk feeds all 3 irreps (3 A-tile
//    buffers + acc[3][4][4]) -> W stagings 38->18, syncthreads 76->36.
// Per block: 32 tokens, 8 warps (2 m16-tiles x 4 n32-quarters), 2 CTAs/SM.
// ============================================================================

#define THREADS 256
#define TOK     32
#define SAU     20     // A tile stride (u32 pairs): frag banks 20*grp+qd distinct
#define SWN     136    // W tile stride (u32 pairs): frag banks 8*qd+grp distinct
#define SP0F    140    // P0 stride (floats)
#define SP1F    396    // P1 stride (floats)

// smem byte offsets
#define OFF_A   0          // 3 x (hi 2560 + lo 2560) = 15360
#define OFF_WH  15360      // 16*136*4 = 8704
#define OFF_WL  24064
#define OFF_P0  32768      // 32*140*4 = 17920
#define OFF_P1  50688      // 32*396*4 = 50688
#define SMEM_BYTES 101376

#define WTILE_U32 2176     // 16*136
__device__ __align__(16) uint32_t g_wh[18 * WTILE_U32];
__device__ __align__(16) uint32_t g_wl[18 * WTILE_U32];

__device__ __forceinline__ uint32_t pack2(float v0, float v1) {
    __nv_bfloat162 p = __floats2bfloat162_rn(v0, v1);   // v0 -> low half
    return *(uint32_t*)&p;
}

__device__ __forceinline__ void split_pair(float v0, float v1,
                                           uint32_t& h, uint32_t& l) {
    h = pack2(v0, v1);
    float h0 = __uint_as_float(h << 16);
    float h1 = __uint_as_float(h & 0xffff0000u);
    l = pack2(v0 - h0, v1 - h1);
}

// ---------------- prep kernel: split all 18 W chunk-tiles once ----------------
// tile 0-3: [W0l|W0r] k-slices; 4-7: [W1l|W1r]; 8-11: W0o; 12-17: W1o.
__global__ void prep_w_kernel(const float* __restrict__ W0l,
                              const float* __restrict__ W0r,
                              const float* __restrict__ W1l,
                              const float* __restrict__ W1r,
                              const float* __restrict__ W0o,
                              const float* __restrict__ W1o) {
    int e = blockIdx.x * blockDim.x + threadIdx.x;   // 0..36863
    int n    = e & 127;
    int kp   = (e >> 7) & 15;
    int tile = e >> 11;
    const float* src;
    int kb;
    if (tile < 4)       { kb = tile * 32;        src = (n < 64) ? W0l + n * 128 : W0r + (n - 64) * 128; }
    else if (tile < 8)  { kb = (tile - 4) * 32;  src = (n < 64) ? W1l + n * 128 : W1r + (n - 64) * 128; }
    else if (tile < 12) { kb = (tile - 8) * 32;  src = W0o + n * 128; }
    else                { kb = (tile - 12) * 32; src = W1o + n * 192; }
    float2 v = *(const float2*)(src + kb + 2 * kp);
    uint32_t h, l; split_pair(v.x, v.y, h, l);
    g_wh[tile * WTILE_U32 + kp * 136 + n] = h;
    g_wl[tile * WTILE_U32 + kp * 136 + n] = l;
}

// ---------------- main kernel helpers ----------------
__device__ __forceinline__ void mma16(float (&c)[4], const uint32_t (&a)[4],
                                      uint32_t b0, uint32_t b1) {
    asm volatile(
        "mma.sync.aligned.m16n8k16.row.col.f32.bf16.bf16.f32 "
        "{%0,%1,%2,%3}, {%4,%5,%6,%7}, {%8,%9}, {%0,%1,%2,%3};"
        : "+f"(c[0]), "+f"(c[1]), "+f"(c[2]), "+f"(c[3])
        : "r"(a[0]), "r"(a[1]), "r"(a[2]), "r"(a[3]), "r"(b0), "r"(b1));
}

__device__ __forceinline__ void gemm_chunk(float (&acc)[4][4],
        const uint32_t* __restrict__ aH, const uint32_t* __restrict__ aL,
        const uint32_t* __restrict__ wH, const uint32_t* __restrict__ wL,
        int mrow0, int nb, int lane) {
    const int grp = lane >> 2, qd = lane & 3;
    const uint32_t* pah = aH + (mrow0 + grp) * SAU + qd;
    const uint32_t* pal = aL + (mrow0 + grp) * SAU + qd;
#pragma unroll
    for (int ks = 0; ks < 2; ++ks) {
        uint32_t ah[4], al[4];
        ah[0] = pah[8 * ks];           ah[1] = pah[8 * SAU + 8 * ks];
        ah[2] = pah[8 * ks + 4];       ah[3] = pah[8 * SAU + 8 * ks + 4];
        al[0] = pal[8 * ks];           al[1] = pal[8 * SAU + 8 * ks];
        al[2] = pal[8 * ks + 4];       al[3] = pal[8 * SAU + 8 * ks + 4];
        const uint32_t* pwh = wH + (8 * ks + qd) * SWN + nb + grp;
        const uint32_t* pwl = wL + (8 * ks + qd) * SWN + nb + grp;
#pragma unroll
        for (int nt = 0; nt < 4; ++nt) {
            uint32_t bh0 = pwh[8 * nt], bh1 = pwh[4 * SWN + 8 * nt];
            uint32_t bl0 = pwl[8 * nt], bl1 = pwl[4 * SWN + 8 * nt];
            mma16(acc[nt], ah, bh0, bh1);
            mma16(acc[nt], ah, bl0, bl1);
            mma16(acc[nt], al, bh0, bh1);
        }
    }
}

// Stage pre-split W tile: pure uint4 copy (hi+lo = 1024 uint4, 4/thread).
__device__ __forceinline__ void stage_W_pre(int tile,
                                            uint32_t* __restrict__ wH,
                                            uint32_t* __restrict__ wL, int tid) {
    const uint4* sh = (const uint4*)(g_wh + tile * WTILE_U32);
    const uint4* sl = (const uint4*)(g_wl + tile * WTILE_U32);
    uint4* dh = (uint4*)wH;
    uint4* dl = (uint4*)wL;
#pragma unroll
    for (int it = 0; it < 2; ++it) {
        int idx = tid + it * THREADS;        // 0..511 : row 0..15, quad 0..31
        int row = idx >> 5, q = idx & 31;
        dh[row * 34 + q] = sh[row * 34 + q];
        dl[row * 34 + q] = sl[row * 34 + q];
    }
}

// Stage A chunk from gmem: 32 tokens x 16 k-pairs, split.
__device__ __forceinline__ void stage_A_g(const float* __restrict__ src, int ld,
                                          uint32_t* __restrict__ aH,
                                          uint32_t* __restrict__ aL, int tid) {
#pragma unroll
    for (int it = 0; it < 2; ++it) {
        int e  = tid + it * THREADS;                 // 0..511
        int kp = (e & 3) | (((e >> 5) & 3) << 2);    // 0..15
        int t  = ((e >> 2) & 7) | ((e >> 7) << 3);   // 0..31
        float2 v = *(const float2*)(src + (long)t * ld + 2 * kp);
        uint32_t h, l; split_pair(v.x, v.y, h, l);
        aH[t * SAU + kp] = h;
        aL[t * SAU + kp] = l;
    }
}

#define ZERO4(acc) do {                                      \
    _Pragma("unroll") for (int _n = 0; _n < 4; ++_n)         \
    _Pragma("unroll") for (int _m = 0; _m < 4; ++_m)         \
        (acc)[_n][_m] = 0.f;                                 \
} while (0)

__global__ __launch_bounds__(THREADS, 2)
void etp_bf16_kernel(const float* __restrict__ z0, const float* __restrict__ z1,
                     const float* __restrict__ b0l, const float* __restrict__ b0r,
                     const float* __restrict__ b0o,
                     float* __restrict__ out0, float* __restrict__ out1) {
    extern __shared__ char smem[];
    uint32_t* aBase = (uint32_t*)(smem + OFF_A);     // 3 x (hi 640 | lo 640) u32
    uint32_t* wH    = (uint32_t*)(smem + OFF_WH);
    uint32_t* wL    = (uint32_t*)(smem + OFF_WL);
    float*    sP0   = (float*)(smem + OFF_P0);
    float*    sP1   = (float*)(smem + OFF_P1);

    const int tid  = threadIdx.x;
    const int lane = tid & 31;
    const int warp = tid >> 5;
    const int grp  = lane >> 2, qd = lane & 3;
    const int mrow0 = (warp & 1) * 16;
    const int nb    = (warp >> 1) * 32;
    const long tokbase = (long)blockIdx.x * TOK;

    uint32_t* aH0 = aBase;         uint32_t* aL0 = aBase + 640;

    // ================= proj0: P0 = z0 @ [W0l|W0r]^T + bias =================
    {
        float acc[4][4]; ZERO4(acc);
        for (int c = 0; c < 4; ++c) {
            __syncthreads();
            stage_A_g(z0 + tokbase * 128 + c * 32, 128, aH0, aL0, tid);
            stage_W_pre(c, wH, wL, tid);
            __syncthreads();
            gemm_chunk(acc, aH0, aL0, wH, wL, mrow0, nb, lane);
        }
#pragma unroll
        for (int nt = 0; nt < 4; ++nt) {
            int col = nb + nt * 8 + 2 * qd;
            float bx = (col < 64) ? b0l[col] : b0r[col - 64];
            float by = (col < 64) ? b0l[col + 1] : b0r[col - 63];
            *(float2*)&sP0[(mrow0 + grp) * SP0F + col] =
                make_float2(acc[0 * 0 + nt][0] + bx, acc[nt][1] + by);
            *(float2*)&sP0[(mrow0 + grp + 8) * SP0F + col] =
                make_float2(acc[nt][2] + bx, acc[nt][3] + by);
        }
    }

    // ====== proj1: P1_i = z1_i @ [W1l|W1r]^T  (one W chunk -> all 3 i) ======
    {
        float acc3[3][4][4];
#pragma unroll
        for (int i = 0; i < 3; ++i) ZERO4(acc3[i]);
        for (int c = 0; c < 4; ++c) {
            __syncthreads();
            stage_W_pre(4 + c, wH, wL, tid);
#pragma unroll
            for (int i = 0; i < 3; ++i)
                stage_A_g(z1 + tokbase * 384 + i * 128 + c * 32, 384,
                          aBase + i * 1280, aBase + i * 1280 + 640, tid);
            __syncthreads();
#pragma unroll
            for (int i = 0; i < 3; ++i)
                gemm_chunk(acc3[i], aBase + i * 1280, aBase + i * 1280 + 640,
                           wH, wL, mrow0, nb, lane);
        }
#pragma unroll
        for (int i = 0; i < 3; ++i)
#pragma unroll
            for (int nt = 0; nt < 4; ++nt) {
                int col = i * 128 + nb + nt * 8 + 2 * qd;
                *(float2*)&sP1[(mrow0 + grp) * SP1F + col] =
                    make_float2(acc3[i][nt][0], acc3[i][nt][1]);
                *(float2*)&sP1[(mrow0 + grp + 8) * SP1F + col] =
                    make_float2(acc3[i][nt][2], acc3[i][nt][3]);
            }
    }

    // ================= out0 = [p00 | p110] @ W0o^T + b0o =================
    {
        float acc[4][4]; ZERO4(acc);
        for (int c = 0; c < 4; ++c) {
            __syncthreads();
            stage_W_pre(8 + c, wH, wL, tid);
            const int cb = c * 32;
#pragma unroll
            for (int it = 0; it < 2; ++it) {
                int e  = tid + it * THREADS;
                int kp = (e & 3) | (((e >> 5) & 3) << 2);
                int t  = ((e >> 2) & 7) | ((e >> 7) << 3);
                int k  = cb + 2 * kp;
                float v0, v1;
                if (cb < 64) {
                    const float* p = &sP0[t * SP0F];
                    v0 = p[k] * p[64 + k];
                    v1 = p[k + 1] * p[64 + k + 1];
                } else {
                    int r = k - 64;
                    const float* p = &sP1[t * SP1F];
                    v0 = p[r] * p[64 + r] + p[128 + r] * p[192 + r]
                       + p[256 + r] * p[320 + r];
                    v1 = p[r + 1] * p[65 + r] + p[129 + r] * p[193 + r]
                       + p[257 + r] * p[321 + r];
                }
                uint32_t h, l; split_pair(v0, v1, h, l);
                aH0[t * SAU + kp] = h;
                aL0[t * SAU + kp] = l;
            }
            __syncthreads();
            gemm_chunk(acc, aH0, aL0, wH, wL, mrow0, nb, lane);
        }
#pragma unroll
        for (int nt = 0; nt < 4; ++nt) {
            int col = nb + nt * 8 + 2 * qd;
            float2 b = *(const float2*)&b0o[col];
            *(float2*)&out0[(tokbase + mrow0 + grp) * 128 + col] =
                make_float2(acc[nt][0] + b.x, acc[nt][1] + b.y);
            *(float2*)&out0[(tokbase + mrow0 + grp + 8) * 128 + col] =
                make_float2(acc[nt][2] + b.x, acc[nt][3] + b.y);
        }
    }

    // ==== out1_i = [q011|q101|q111]_i @ W1o^T  (one W chunk -> all 3 i) ====
    {
        float acc3[3][4][4];
#pragma unroll
        for (int i = 0; i < 3; ++i) ZERO4(acc3[i]);
        for (int cc = 0; cc < 6; ++cc) {
            __syncthreads();
            stage_W_pre(12 + cc, wH, wL, tid);
            const int cb = cc * 32;
#pragma unroll
            for (int i = 0; i < 3; ++i) {
                const int i1 = (i + 1 < 3) ? i + 1 : i - 2;
                const int i2 = (i + 2 < 3) ? i + 2 : i - 1;
                uint32_t* aH = aBase + i * 1280;
                uint32_t* aL = aH + 640;
#pragma unroll
                for (int it = 0; it < 2; ++it) {
                    int e  = tid + it * THREADS;
                    int kp = (e & 3) | (((e >> 5) & 3) << 2);
                    int t  = ((e >> 2) & 7) | ((e >> 7) << 3);
                    int k  = cb + 2 * kp;
                    const float* p  = &sP1[t * SP1F];
                    const float* p0 = &sP0[t * SP0F];
                    float v0, v1;
                    if (cb < 64) {                        // q011 = P0l * P1r_i
                        v0 = p0[k] * p[i * 128 + 64 + k];
                        v1 = p0[k + 1] * p[i * 128 + 65 + k];
                    } else if (cb < 128) {                // q101 = P1l_i * P0r
                        int r = k - 64;
                        v0 = p[i * 128 + r] * p0[64 + r];
                        v1 = p[i * 128 + r + 1] * p0[65 + r];
                    } else {                              // q111 = cross_i
                        int r = k - 128;
                        v0 = p[i1 * 128 + r] * p[i2 * 128 + 64 + r]
                           - p[i2 * 128 + r] * p[i1 * 128 + 64 + r];
                        v1 = p[i1 * 128 + r + 1] * p[i2 * 128 + 65 + r]
                           - p[i2 * 128 + r + 1] * p[i1 * 128 + 65 + r];
                    }
                    uint32_t h, l; split_pair(v0, v1, h, l);
                    aH[t * SAU + kp] = h;
                    aL[t * SAU + kp] = l;
                }
            }
            __syncthreads();
#pragma unroll
            for (int i = 0; i < 3; ++i)
                gemm_chunk(acc3[i], aBase + i * 1280, aBase + i * 1280 + 640,
                           wH, wL, mrow0, nb, lane);
        }
#pragma unroll
        for (int i = 0; i < 3; ++i)
#pragma unroll
            for (int nt = 0; nt < 4; ++nt) {
                int col = nb + nt * 8 + 2 * qd;
                *(float2*)&out1[(tokbase + mrow0 + grp) * 384 + i * 128 + col] =
                    make_float2(acc3[i][nt][0], acc3[i][nt][1]);
                *(float2*)&out1[(tokbase + mrow0 + grp + 8) * 384 + i * 128 + col] =
                    make_float2(acc3[i][nt][2], acc3[i][nt][3]);
            }
    }
}

extern "C" void kernel_launch(void* const* d_in, const int* in_sizes, int n_in,
                              void* d_out, int out_size) {
    const float* z0  = (const float*)d_in[0];
    const float* z1  = (const float*)d_in[1];
    const float* W0l = (const float*)d_in[2];
    const float* b0l = (const float*)d_in[3];
    const float* W0r = (const float*)d_in[4];
    const float* b0r = (const float*)d_in[5];
    const float* W1l = (const float*)d_in[6];
    const float* W1r = (const float*)d_in[7];
    const float* W0o = (const float*)d_in[8];
    const float* b0o = (const float*)d_in[9];
    const float* W1o = (const float*)d_in[10];

    const int BN = in_sizes[0] / 128;            // 65536 tokens
    float* out0 = (float*)d_out;
    float* out1 = (float*)d_out + (long)BN * 128;

    prep_w_kernel<<<144, 256>>>(W0l, W0r, W1l, W1r, W0o, W1o);

    cudaFuncSetAttribute(etp_bf16_kernel,
                         cudaFuncAttributeMaxDynamicSharedMemorySize, SMEM_BYTES);

    dim3 grid(BN / TOK);    // 2048
    dim3 block(THREADS);
    etp_bf16_kernel<<<grid, block, SMEM_BYTES>>>(z0, z1, b0l, b0r, b0o,
                                                 out0, out1);
}

// round 12
// speedup vs baseline: 3.1380x; 1.1745x over previous
#include <cuda_runtime.h>
#include <cuda_bf16.h>
#include <cstdint>

// ============================================================================
// ElementwiseTensorProducts — mma.sync.m16n8k16 bf16, 2-way split (hh+hl+lh).
//
// R12 changes vs R11 (276us):
//  * W fragments hoisted across the 3-irrep loop: per chunk, A frags for all
//    3 i are held in registers and each W frag is loaded from smem ONCE
//    (frag LDS per proj1/out1 chunk-warp: 144 -> 80 wavefronts).
//  * W tile staging via cp.async.cg (global->smem direct, no RF round trip).
// Weights pre-split once per launch into __device__ scratch (prep kernel).
// Per block: 32 tokens, 8 warps (2 m16-tiles x 4 n32-quarters), 2 CTAs/SM.
// ============================================================================

#define THREADS 256
#define TOK     32
#define SAU     20     // A tile stride (u32 pairs): frag banks 20*grp+qd distinct
#define SWN     136    // W tile stride (u32 pairs): frag banks 8*qd+grp distinct
#define SP0F    140    // P0 stride (floats)
#define SP1F    396    // P1 stride (floats)

// smem byte offsets
#define OFF_A   0          // 3 x (hi 2560 + lo 2560) = 15360
#define OFF_WH  15360      // 16*136*4 = 8704
#define OFF_WL  24064
#define OFF_P0  32768      // 32*140*4 = 17920
#define OFF_P1  50688      // 32*396*4 = 50688
#define SMEM_BYTES 101376

#define WTILE_U32 2176     // 16*136
__device__ __align__(16) uint32_t g_wh[18 * WTILE_U32];
__device__ __align__(16) uint32_t g_wl[18 * WTILE_U32];

__device__ __forceinline__ uint32_t pack2(float v0, float v1) {
    __nv_bfloat162 p = __floats2bfloat162_rn(v0, v1);   // v0 -> low half
    return *(uint32_t*)&p;
}

__device__ __forceinline__ void split_pair(float v0, float v1,
                                           uint32_t& h, uint32_t& l) {
    h = pack2(v0, v1);
    float h0 = __uint_as_float(h << 16);
    float h1 = __uint_as_float(h & 0xffff0000u);
    l = pack2(v0 - h0, v1 - h1);
}

// ---------------- prep kernel: split all 18 W chunk-tiles once ----------------
// tile 0-3: [W0l|W0r] k-slices; 4-7: [W1l|W1r]; 8-11: W0o; 12-17: W1o.
__global__ void prep_w_kernel(const float* __restrict__ W0l,
                              const float* __restrict__ W0r,
                              const float* __restrict__ W1l,
                              const float* __restrict__ W1r,
                              const float* __restrict__ W0o,
                              const float* __restrict__ W1o) {
    int e = blockIdx.x * blockDim.x + threadIdx.x;   // 0..36863
    int n    = e & 127;
    int kp   = (e >> 7) & 15;
    int tile = e >> 11;
    const float* src;
    int kb;
    if (tile < 4)       { kb = tile * 32;        src = (n < 64) ? W0l + n * 128 : W0r + (n - 64) * 128; }
    else if (tile < 8)  { kb = (tile - 4) * 32;  src = (n < 64) ? W1l + n * 128 : W1r + (n - 64) * 128; }
    else if (tile < 12) { kb = (tile - 8) * 32;  src = W0o + n * 128; }
    else                { kb = (tile - 12) * 32; src = W1o + n * 192; }
    float2 v = *(const float2*)(src + kb + 2 * kp);
    uint32_t h, l; split_pair(v.x, v.y, h, l);
    g_wh[tile * WTILE_U32 + kp * 136 + n] = h;
    g_wl[tile * WTILE_U32 + kp * 136 + n] = l;
}

// ---------------- main kernel helpers ----------------
__device__ __forceinline__ void mma16(float (&c)[4], const uint32_t (&a)[4],
                                      uint32_t b0, uint32_t b1) {
    asm volatile(
        "mma.sync.aligned.m16n8k16.row.col.f32.bf16.bf16.f32 "
        "{%0,%1,%2,%3}, {%4,%5,%6,%7}, {%8,%9}, {%0,%1,%2,%3};"
        : "+f"(c[0]), "+f"(c[1]), "+f"(c[2]), "+f"(c[3])
        : "r"(a[0]), "r"(a[1]), "r"(a[2]), "r"(a[3]), "r"(b0), "r"(b1));
}

// NI irreps per staged W chunk. A frags for all NI held across the nt loop;
// each W frag loaded from smem exactly once per chunk.
template <int NI>
__device__ __forceinline__ void gemm_chunk_multi(float (&acc)[NI][4][4],
        const uint32_t* __restrict__ aBase,   // per-i stride 1280; lo at +640
        const uint32_t* __restrict__ wH, const uint32_t* __restrict__ wL,
        int mrow0, int nb, int lane) {
    const int grp = lane >> 2, qd = lane & 3;
#pragma unroll
    for (int ks = 0; ks < 2; ++ks) {
        uint32_t ah[NI][4], al[NI][4];
#pragma unroll
        for (int i = 0; i < NI; ++i) {
            const uint32_t* pah = aBase + i * 1280 + (mrow0 + grp) * SAU + qd;
            const uint32_t* pal = pah + 640;
            ah[i][0] = pah[8 * ks];         ah[i][1] = pah[8 * SAU + 8 * ks];
            ah[i][2] = pah[8 * ks + 4];     ah[i][3] = pah[8 * SAU + 8 * ks + 4];
            al[i][0] = pal[8 * ks];         al[i][1] = pal[8 * SAU + 8 * ks];
            al[i][2] = pal[8 * ks + 4];     al[i][3] = pal[8 * SAU + 8 * ks + 4];
        }
#pragma unroll
        for (int nt = 0; nt < 4; ++nt) {
            const uint32_t* pwh = wH + (8 * ks + qd) * SWN + nb + grp + 8 * nt;
            const uint32_t* pwl = wL + (8 * ks + qd) * SWN + nb + grp + 8 * nt;
            uint32_t bh0 = pwh[0], bh1 = pwh[4 * SWN];
            uint32_t bl0 = pwl[0], bl1 = pwl[4 * SWN];
#pragma unroll
            for (int i = 0; i < NI; ++i) {
                mma16(acc[i][nt], ah[i], bh0, bh1);
                mma16(acc[i][nt], ah[i], bl0, bl1);
                mma16(acc[i][nt], al[i], bh0, bh1);
            }
        }
    }
}

// Stage pre-split W tile via cp.async (16 rows x 32 uint4 used per buffer).
__device__ __forceinline__ void stage_W_cp(int tile,
                                           uint32_t* __restrict__ wH,
                                           uint32_t* __restrict__ wL, int tid) {
    const uint4* sh = (const uint4*)(g_wh + tile * WTILE_U32);
    const uint4* sl = (const uint4*)(g_wl + tile * WTILE_U32);
#pragma unroll
    for (int it = 0; it < 2; ++it) {
        int idx = tid + it * THREADS;        // 0..511 : row 0..15, quad 0..31
        int row = idx >> 5, q = idx & 31;
        uint32_t dh = (uint32_t)__cvta_generic_to_shared((uint4*)wH + row * 34 + q);
        uint32_t dl = (uint32_t)__cvta_generic_to_shared((uint4*)wL + row * 34 + q);
        asm volatile("cp.async.cg.shared.global [%0], [%1], 16;"
                     :: "r"(dh), "l"(sh + row * 34 + q));
        asm volatile("cp.async.cg.shared.global [%0], [%1], 16;"
                     :: "r"(dl), "l"(sl + row * 34 + q));
    }
}

#define CP_COMMIT_WAIT() do {                                     \
    asm volatile("cp.async.commit_group;" ::: "memory");          \
    asm volatile("cp.async.wait_group 0;" ::: "memory");          \
} while (0)

// Stage A chunk from gmem: 32 tokens x 16 k-pairs, split.
__device__ __forceinline__ void stage_A_g(const float* __restrict__ src, int ld,
                                          uint32_t* __restrict__ aH,
                                          uint32_t* __restrict__ aL, int tid) {
#pragma unroll
    for (int it = 0; it < 2; ++it) {
        int e  = tid + it * THREADS;                 // 0..511
        int kp = (e & 3) | (((e >> 5) & 3) << 2);    // 0..15
        int t  = ((e >> 2) & 7) | ((e >> 7) << 3);   // 0..31
        float2 v = *(const float2*)(src + (long)t * ld + 2 * kp);
        uint32_t h, l; split_pair(v.x, v.y, h, l);
        aH[t * SAU + kp] = h;
        aL[t * SAU + kp] = l;
    }
}

#define ZERO4(acc) do {                                      \
    _Pragma("unroll") for (int _n = 0; _n < 4; ++_n)         \
    _Pragma("unroll") for (int _m = 0; _m < 4; ++_m)         \
        (acc)[_n][_m] = 0.f;                                 \
} while (0)

__global__ __launch_bounds__(THREADS, 2)
void etp_bf16_kernel(const float* __restrict__ z0, const float* __restrict__ z1,
                     const float* __restrict__ b0l, const float* __restrict__ b0r,
                     const float* __restrict__ b0o,
                     float* __restrict__ out0, float* __restrict__ out1) {
    extern __shared__ char smem[];
    uint32_t* aBase = (uint32_t*)(smem + OFF_A);     // 3 x (hi 640 | lo 640) u32
    uint32_t* wH    = (uint32_t*)(smem + OFF_WH);
    uint32_t* wL    = (uint32_t*)(smem + OFF_WL);
    float*    sP0   = (float*)(smem + OFF_P0);
    float*    sP1   = (float*)(smem + OFF_P1);

    const int tid  = threadIdx.x;
    const int lane = tid & 31;
    const int warp = tid >> 5;
    const int grp  = lane >> 2, qd = lane & 3;
    const int mrow0 = (warp & 1) * 16;
    const int nb    = (warp >> 1) * 32;
    const long tokbase = (long)blockIdx.x * TOK;

    uint32_t* aH0 = aBase;
    uint32_t* aL0 = aBase + 640;

    // ================= proj0: P0 = z0 @ [W0l|W0r]^T + bias =================
    {
        float acc[1][4][4]; ZERO4(acc[0]);
        for (int c = 0; c < 4; ++c) {
            __syncthreads();
            stage_W_cp(c, wH, wL, tid);
            stage_A_g(z0 + tokbase * 128 + c * 32, 128, aH0, aL0, tid);
            CP_COMMIT_WAIT();
            __syncthreads();
            gemm_chunk_multi<1>(acc, aBase, wH, wL, mrow0, nb, lane);
        }
#pragma unroll
        for (int nt = 0; nt < 4; ++nt) {
            int col = nb + nt * 8 + 2 * qd;
            float bx = (col < 64) ? b0l[col] : b0r[col - 64];
            float by = (col < 64) ? b0l[col + 1] : b0r[col - 63];
            *(float2*)&sP0[(mrow0 + grp) * SP0F + col] =
                make_float2(acc[0][nt][0] + bx, acc[0][nt][1] + by);
            *(float2*)&sP0[(mrow0 + grp + 8) * SP0F + col] =
                make_float2(acc[0][nt][2] + bx, acc[0][nt][3] + by);
        }
    }

    // ====== proj1: P1_i = z1_i @ [W1l|W1r]^T  (one W chunk -> all 3 i) ======
    {
        float acc3[3][4][4];
#pragma unroll
        for (int i = 0; i < 3; ++i) ZERO4(acc3[i]);
        for (int c = 0; c < 4; ++c) {
            __syncthreads();
            stage_W_cp(4 + c, wH, wL, tid);
#pragma unroll
            for (int i = 0; i < 3; ++i)
                stage_A_g(z1 + tokbase * 384 + i * 128 + c * 32, 384,
                          aBase + i * 1280, aBase + i * 1280 + 640, tid);
            CP_COMMIT_WAIT();
            __syncthreads();
            gemm_chunk_multi<3>(acc3, aBase, wH, wL, mrow0, nb, lane);
        }
#pragma unroll
        for (int i = 0; i < 3; ++i)
#pragma unroll
            for (int nt = 0; nt < 4; ++nt) {
                int col = i * 128 + nb + nt * 8 + 2 * qd;
                *(float2*)&sP1[(mrow0 + grp) * SP1F + col] =
                    make_float2(acc3[i][nt][0], acc3[i][nt][1]);
                *(float2*)&sP1[(mrow0 + grp + 8) * SP1F + col] =
                    make_float2(acc3[i][nt][2], acc3[i][nt][3]);
            }
    }

    // ================= out0 = [p00 | p110] @ W0o^T + b0o =================
    {
        float acc[1][4][4]; ZERO4(acc[0]);
        for (int c = 0; c < 4; ++c) {
            __syncthreads();
            stage_W_cp(8 + c, wH, wL, tid);
            const int cb = c * 32;
#pragma unroll
            for (int it = 0; it < 2; ++it) {
                int e  = tid + it * THREADS;
                int kp = (e & 3) | (((e >> 5) & 3) << 2);
                int t  = ((e >> 2) & 7) | ((e >> 7) << 3);
                int k  = cb + 2 * kp;
                float v0, v1;
                if (cb < 64) {                            // p00 = P0l * P0r
                    const float* p = &sP0[t * SP0F];
                    v0 = p[k] * p[64 + k];
                    v1 = p[k + 1] * p[64 + k + 1];
                } else {                                  // p110 = sum_i P1l*P1r
                    int r = k - 64;
                    const float* p = &sP1[t * SP1F];
                    v0 = p[r] * p[64 + r] + p[128 + r] * p[192 + r]
                       + p[256 + r] * p[320 + r];
                    v1 = p[r + 1] * p[65 + r] + p[129 + r] * p[193 + r]
                       + p[257 + r] * p[321 + r];
                }
                uint32_t h, l; split_pair(v0, v1, h, l);
                aH0[t * SAU + kp] = h;
                aL0[t * SAU + kp] = l;
            }
            CP_COMMIT_WAIT();
            __syncthreads();
            gemm_chunk_multi<1>(acc, aBase, wH, wL, mrow0, nb, lane);
        }
#pragma unroll
        for (int nt = 0; nt < 4; ++nt) {
            int col = nb + nt * 8 + 2 * qd;
            float2 b = *(const float2*)&b0o[col];
            *(float2*)&out0[(tokbase + mrow0 + grp) * 128 + col] =
                make_float2(acc[0][nt][0] + b.x, acc[0][nt][1] + b.y);
            *(float2*)&out0[(tokbase + mrow0 + grp + 8) * 128 + col] =
                make_float2(acc[0][nt][2] + b.x, acc[0][nt][3] + b.y);
        }
    }

    // ==== out1_i = [q011|q101|q111]_i @ W1o^T  (one W chunk -> all 3 i) ====
    {
        float acc3[3][4][4];
#pragma unroll
        for (int i = 0; i < 3; ++i) ZERO4(acc3[i]);
        for (int cc = 0; cc < 6; ++cc) {
            __syncthreads();
            stage_W_cp(12 + cc, wH, wL, tid);
            const int cb = cc * 32;
#pragma unroll
            for (int i = 0; i < 3; ++i) {
                const int i1 = (i + 1 < 3) ? i + 1 : i - 2;
                const int i2 = (i + 2 < 3) ? i + 2 : i - 1;
                uint32_t* aH = aBase + i * 1280;
                uint32_t* aL = aH + 640;
#pragma unroll
                for (int it = 0; it < 2; ++it) {
                    int e  = tid + it * THREADS;
                    int kp = (e & 3) | (((e >> 5) & 3) << 2);
                    int t  = ((e >> 2) & 7) | ((e >> 7) << 3);
                    int k  = cb + 2 * kp;
                    const float* p  = &sP1[t * SP1F];
                    const float* p0 = &sP0[t * SP0F];
                    float v0, v1;
                    if (cb < 64) {                        // q011 = P0l * P1r_i
                        v0 = p0[k] * p[i * 128 + 64 + k];
                        v1 = p0[k + 1] * p[i * 128 + 65 + k];
                    } else if (cb < 128) {                // q101 = P1l_i * P0r
                        int r = k - 64;
                        v0 = p[i * 128 + r] * p0[64 + r];
                        v1 = p[i * 128 + r + 1] * p0[65 + r];
                    } else {                              // q111 = cross_i
                        int r = k - 128;
                        v0 = p[i1 * 128 + r] * p[i2 * 128 + 64 + r]
                           - p[i2 * 128 + r] * p[i1 * 128 + 64 + r];
                        v1 = p[i1 * 128 + r + 1] * p[i2 * 128 + 65 + r]
                           - p[i2 * 128 + r + 1] * p[i1 * 128 + 65 + r];
                    }
                    uint32_t h, l; split_pair(v0, v1, h, l);
                    aH[t * SAU + kp] = h;
                    aL[t * SAU + kp] = l;
                }
            }
            CP_COMMIT_WAIT();
            __syncthreads();
            gemm_chunk_multi<3>(acc3, aBase, wH, wL, mrow0, nb, lane);
        }
#pragma unroll
        for (int i = 0; i < 3; ++i)
#pragma unroll
            for (int nt = 0; nt < 4; ++nt) {
                int col = nb + nt * 8 + 2 * qd;
                *(float2*)&out1[(tokbase + mrow0 + grp) * 384 + i * 128 + col] =
                    make_float2(acc3[i][nt][0], acc3[i][nt][1]);
                *(float2*)&out1[(tokbase + mrow0 + grp + 8) * 384 + i * 128 + col] =
                    make_float2(acc3[i][nt][2], acc3[i][nt][3]);
            }
    }
}

extern "C" void kernel_launch(void* const* d_in, const int* in_sizes, int n_in,
                              void* d_out, int out_size) {
    const float* z0  = (const float*)d_in[0];
    const float* z1  = (const float*)d_in[1];
    const float* W0l = (const float*)d_in[2];
    const float* b0l = (const float*)d_in[3];
    const float* W0r = (const float*)d_in[4];
    const float* b0r = (const float*)d_in[5];
    const float* W1l = (const float*)d_in[6];
    const float* W1r = (const float*)d_in[7];
    const float* W0o = (const float*)d_in[8];
    const float* b0o = (const float*)d_in[9];
    const float* W1o = (const float*)d_in[10];

    const int BN = in_sizes[0] / 128;            // 65536 tokens
    float* out0 = (float*)d_out;
    float* out1 = (float*)d_out + (long)BN * 128;

    prep_w_kernel<<<144, 256>>>(W0l, W0r, W1l, W1r, W0o, W1o);

    cudaFuncSetAttribute(etp_bf16_kernel,
                         cudaFuncAttributeMaxDynamicSharedMemorySize, SMEM_BYTES);

    dim3 grid(BN / TOK);    // 2048
    dim3 block(THREADS);
    etp_bf16_kernel<<<grid, block, SMEM_BYTES>>>(z0, z1, b0l, b0r, b0o,
                                                 out0, out1);
}

// round 13
// speedup vs baseline: 3.2771x; 1.0443x over previous
#include <cuda_runtime.h>
#include <cuda_bf16.h>
#include <cstdint>

// ============================================================================
// ElementwiseTensorProducts — mma.sync.m16n8k16 bf16, 2-way split (hh+hl+lh).
//
// R13 changes vs R12 (235us):
//  * Register prefetch of gmem A chunks (z0/z1) one chunk ahead: LDG issued
//    right after the previous chunk's commit, consumed next iteration ->
//    DRAM latency hidden behind wait+sync+gemm+W-stage. Cross-phase prefetch
//    (proj1 chunk 0 issued during proj0's last chunk).
// Carried from R11/R12: weights pre-split once into __device__ scratch in
// smem tile layout (prep kernel); W staging via cp.async.cg; W fragments
// hoisted across the 3-irrep loop.
// Per block: 32 tokens, 8 warps (2 m16-tiles x 4 n32-quarters), 2 CTAs/SM.
// ============================================================================

#define THREADS 256
#define TOK     32
#define SAU     20     // A tile stride (u32 pairs): frag banks 20*grp+qd distinct
#define SWN     136    // W tile stride (u32 pairs): frag banks 8*qd+grp distinct
#define SP0F    140    // P0 stride (floats)
#define SP1F    396    // P1 stride (floats)

// smem byte offsets
#define OFF_A   0          // 3 x (hi 2560 + lo 2560) = 15360
#define OFF_WH  15360      // 16*136*4 = 8704
#define OFF_WL  24064
#define OFF_P0  32768      // 32*140*4 = 17920
#define OFF_P1  50688      // 32*396*4 = 50688
#define SMEM_BYTES 101376

#define WTILE_U32 2176     // 16*136
__device__ __align__(16) uint32_t g_wh[18 * WTILE_U32];
__device__ __align__(16) uint32_t g_wl[18 * WTILE_U32];

__device__ __forceinline__ uint32_t pack2(float v0, float v1) {
    __nv_bfloat162 p = __floats2bfloat162_rn(v0, v1);   // v0 -> low half
    return *(uint32_t*)&p;
}

__device__ __forceinline__ void split_pair(float v0, float v1,
                                           uint32_t& h, uint32_t& l) {
    h = pack2(v0, v1);
    float h0 = __uint_as_float(h << 16);
    float h1 = __uint_as_float(h & 0xffff0000u);
    l = pack2(v0 - h0, v1 - h1);
}

// ---------------- prep kernel: split all 18 W chunk-tiles once ----------------
// tile 0-3: [W0l|W0r] k-slices; 4-7: [W1l|W1r]; 8-11: W0o; 12-17: W1o.
__global__ void prep_w_kernel(const float* __restrict__ W0l,
                              const float* __restrict__ W0r,
                              const float* __restrict__ W1l,
                              const float* __restrict__ W1r,
                              const float* __restrict__ W0o,
                              const float* __restrict__ W1o) {
    int e = blockIdx.x * blockDim.x + threadIdx.x;   // 0..36863
    int n    = e & 127;
    int kp   = (e >> 7) & 15;
    int tile = e >> 11;
    const float* src;
    int kb;
    if (tile < 4)       { kb = tile * 32;        src = (n < 64) ? W0l + n * 128 : W0r + (n - 64) * 128; }
    else if (tile < 8)  { kb = (tile - 4) * 32;  src = (n < 64) ? W1l + n * 128 : W1r + (n - 64) * 128; }
    else if (tile < 12) { kb = (tile - 8) * 32;  src = W0o + n * 128; }
    else                { kb = (tile - 12) * 32; src = W1o + n * 192; }
    float2 v = *(const float2*)(src + kb + 2 * kp);
    uint32_t h, l; split_pair(v.x, v.y, h, l);
    g_wh[tile * WTILE_U32 + kp * 136 + n] = h;
    g_wl[tile * WTILE_U32 + kp * 136 + n] = l;
}

// ---------------- main kernel helpers ----------------
__device__ __forceinline__ void mma16(float (&c)[4], const uint32_t (&a)[4],
                                      uint32_t b0, uint32_t b1) {
    asm volatile(
        "mma.sync.aligned.m16n8k16.row.col.f32.bf16.bf16.f32 "
        "{%0,%1,%2,%3}, {%4,%5,%6,%7}, {%8,%9}, {%0,%1,%2,%3};"
        : "+f"(c[0]), "+f"(c[1]), "+f"(c[2]), "+f"(c[3])
        : "r"(a[0]), "r"(a[1]), "r"(a[2]), "r"(a[3]), "r"(b0), "r"(b1));
}

// NI irreps per staged W chunk. A frags for all NI held across the nt loop;
// each W frag loaded from smem exactly once per chunk.
template <int NI>
__device__ __forceinline__ void gemm_chunk_multi(float (&acc)[NI][4][4],
        const uint32_t* __restrict__ aBase,   // per-i stride 1280; lo at +640
        const uint32_t* __restrict__ wH, const uint32_t* __restrict__ wL,
        int mrow0, int nb, int lane) {
    const int grp = lane >> 2, qd = lane & 3;
#pragma unroll
    for (int ks = 0; ks < 2; ++ks) {
        uint32_t ah[NI][4], al[NI][4];
#pragma unroll
        for (int i = 0; i < NI; ++i) {
            const uint32_t* pah = aBase + i * 1280 + (mrow0 + grp) * SAU + qd;
            const uint32_t* pal = pah + 640;
            ah[i][0] = pah[8 * ks];         ah[i][1] = pah[8 * SAU + 8 * ks];
            ah[i][2] = pah[8 * ks + 4];     ah[i][3] = pah[8 * SAU + 8 * ks + 4];
            al[i][0] = pal[8 * ks];         al[i][1] = pal[8 * SAU + 8 * ks];
            al[i][2] = pal[8 * ks + 4];     al[i][3] = pal[8 * SAU + 8 * ks + 4];
        }
#pragma unroll
        for (int nt = 0; nt < 4; ++nt) {
            const uint32_t* pwh = wH + (8 * ks + qd) * SWN + nb + grp + 8 * nt;
            const uint32_t* pwl = wL + (8 * ks + qd) * SWN + nb + grp + 8 * nt;
            uint32_t bh0 = pwh[0], bh1 = pwh[4 * SWN];
            uint32_t bl0 = pwl[0], bl1 = pwl[4 * SWN];
#pragma unroll
            for (int i = 0; i < NI; ++i) {
                mma16(acc[i][nt], ah[i], bh0, bh1);
                mma16(acc[i][nt], ah[i], bl0, bl1);
                mma16(acc[i][nt], al[i], bh0, bh1);
            }
        }
    }
}

// Stage pre-split W tile via cp.async (16 rows x 32 uint4 used per buffer).
__device__ __forceinline__ void stage_W_cp(int tile,
                                           uint32_t* __restrict__ wH,
                                           uint32_t* __restrict__ wL, int tid) {
    const uint4* sh = (const uint4*)(g_wh + tile * WTILE_U32);
    const uint4* sl = (const uint4*)(g_wl + tile * WTILE_U32);
#pragma unroll
    for (int it = 0; it < 2; ++it) {
        int idx = tid + it * THREADS;        // 0..511 : row 0..15, quad 0..31
        int row = idx >> 5, q = idx & 31;
        uint32_t dh = (uint32_t)__cvta_generic_to_shared((uint4*)wH + row * 34 + q);
        uint32_t dl = (uint32_t)__cvta_generic_to_shared((uint4*)wL + row * 34 + q);
        asm volatile("cp.async.cg.shared.global [%0], [%1], 16;"
                     :: "r"(dh), "l"(sh + row * 34 + q));
        asm volatile("cp.async.cg.shared.global [%0], [%1], 16;"
                     :: "r"(dl), "l"(sl + row * 34 + q));
    }
}

#define CP_COMMIT_WAIT() do {                                     \
    asm volatile("cp.async.commit_group;" ::: "memory");          \
    asm volatile("cp.async.wait_group 0;" ::: "memory");          \
} while (0)

// -------- A staging split into prefetch (LDG -> regs) + commit (split+STS) ---
__device__ __forceinline__ void prefetch_A(const float* __restrict__ src, int ld,
                                           float2 (&pre)[2], int tid) {
#pragma unroll
    for (int it = 0; it < 2; ++it) {
        int e  = tid + it * THREADS;                 // 0..511
        int kp = (e & 3) | (((e >> 5) & 3) << 2);    // 0..15
        int t  = ((e >> 2) & 7) | ((e >> 7) << 3);   // 0..31
        pre[it] = *(const float2*)(src + (long)t * ld + 2 * kp);
    }
}

__device__ __forceinline__ void commit_A(const float2 (&pre)[2],
                                         uint32_t* __restrict__ aH,
                                         uint32_t* __restrict__ aL, int tid) {
#pragma unroll
    for (int it = 0; it < 2; ++it) {
        int e  = tid + it * THREADS;
        int kp = (e & 3) | (((e >> 5) & 3) << 2);
        int t  = ((e >> 2) & 7) | ((e >> 7) << 3);
        uint32_t h, l; split_pair(pre[it].x, pre[it].y, h, l);
        aH[t * SAU + kp] = h;
        aL[t * SAU + kp] = l;
    }
}

#define ZERO4(acc) do {                                      \
    _Pragma("unroll") for (int _n = 0; _n < 4; ++_n)         \
    _Pragma("unroll") for (int _m = 0; _m < 4; ++_m)         \
        (acc)[_n][_m] = 0.f;                                 \
} while (0)

__global__ __launch_bounds__(THREADS, 2)
void etp_bf16_kernel(const float* __restrict__ z0, const float* __restrict__ z1,
                     const float* __restrict__ b0l, const float* __restrict__ b0r,
                     const float* __restrict__ b0o,
                     float* __restrict__ out0, float* __restrict__ out1) {
    extern __shared__ char smem[];
    uint32_t* aBase = (uint32_t*)(smem + OFF_A);     // 3 x (hi 640 | lo 640) u32
    uint32_t* wH    = (uint32_t*)(smem + OFF_WH);
    uint32_t* wL    = (uint32_t*)(smem + OFF_WL);
    float*    sP0   = (float*)(smem + OFF_P0);
    float*    sP1   = (float*)(smem + OFF_P1);

    const int tid  = threadIdx.x;
    const int lane = tid & 31;
    const int warp = tid >> 5;
    const int grp  = lane >> 2, qd = lane & 3;
    const int mrow0 = (warp & 1) * 16;
    const int nb    = (warp >> 1) * 32;
    const long tokbase = (long)blockIdx.x * TOK;

    uint32_t* aH0 = aBase;
    uint32_t* aL0 = aBase + 640;

    float2 pre1[3][2];   // proj1 prefetch registers (live from end of proj0)

    // ================= proj0: P0 = z0 @ [W0l|W0r]^T + bias =================
    {
        float acc[1][4][4]; ZERO4(acc[0]);
        float2 pre0[2];
        prefetch_A(z0 + tokbase * 128, 128, pre0, tid);
        for (int c = 0; c < 4; ++c) {
            __syncthreads();
            stage_W_cp(c, wH, wL, tid);
            commit_A(pre0, aH0, aL0, tid);
            if (c < 3) {
                prefetch_A(z0 + tokbase * 128 + (c + 1) * 32, 128, pre0, tid);
            } else {
                // cross-phase: issue proj1 chunk-0 loads now
#pragma unroll
                for (int i = 0; i < 3; ++i)
                    prefetch_A(z1 + tokbase * 384 + i * 128, 384, pre1[i], tid);
            }
            CP_COMMIT_WAIT();
            __syncthreads();
            gemm_chunk_multi<1>(acc, aBase, wH, wL, mrow0, nb, lane);
        }
#pragma unroll
        for (int nt = 0; nt < 4; ++nt) {
            int col = nb + nt * 8 + 2 * qd;
            float bx = (col < 64) ? b0l[col] : b0r[col - 64];
            float by = (col < 64) ? b0l[col + 1] : b0r[col - 63];
            *(float2*)&sP0[(mrow0 + grp) * SP0F + col] =
                make_float2(acc[0][nt][0] + bx, acc[0][nt][1] + by);
            *(float2*)&sP0[(mrow0 + grp + 8) * SP0F + col] =
                make_float2(acc[0][nt][2] + bx, acc[0][nt][3] + by);
        }
    }

    // ====== proj1: P1_i = z1_i @ [W1l|W1r]^T  (one W chunk -> all 3 i) ======
    {
        float acc3[3][4][4];
#pragma unroll
        for (int i = 0; i < 3; ++i) ZERO4(acc3[i]);
        for (int c = 0; c < 4; ++c) {
            __syncthreads();
            stage_W_cp(4 + c, wH, wL, tid);
#pragma unroll
            for (int i = 0; i < 3; ++i)
                commit_A(pre1[i], aBase + i * 1280, aBase + i * 1280 + 640, tid);
            if (c < 3) {
#pragma unroll
                for (int i = 0; i < 3; ++i)
                    prefetch_A(z1 + tokbase * 384 + i * 128 + (c + 1) * 32, 384,
                               pre1[i], tid);
            }
            CP_COMMIT_WAIT();
            __syncthreads();
            gemm_chunk_multi<3>(acc3, aBase, wH, wL, mrow0, nb, lane);
        }
#pragma unroll
        for (int i = 0; i < 3; ++i)
#pragma unroll
            for (int nt = 0; nt < 4; ++nt) {
                int col = i * 128 + nb + nt * 8 + 2 * qd;
                *(float2*)&sP1[(mrow0 + grp) * SP1F + col] =
                    make_float2(acc3[i][nt][0], acc3[i][nt][1]);
                *(float2*)&sP1[(mrow0 + grp + 8) * SP1F + col] =
                    make_float2(acc3[i][nt][2], acc3[i][nt][3]);
            }
    }

    // ================= out0 = [p00 | p110] @ W0o^T + b0o =================
    {
        float acc[1][4][4]; ZERO4(acc[0]);
        for (int c = 0; c < 4; ++c) {
            __syncthreads();
            stage_W_cp(8 + c, wH, wL, tid);
            const int cb = c * 32;
#pragma unroll
            for (int it = 0; it < 2; ++it) {
                int e  = tid + it * THREADS;
                int kp = (e & 3) | (((e >> 5) & 3) << 2);
                int t  = ((e >> 2) & 7) | ((e >> 7) << 3);
                int k  = cb + 2 * kp;
                float v0, v1;
                if (cb < 64) {                            // p00 = P0l * P0r
                    const float* p = &sP0[t * SP0F];
                    v0 = p[k] * p[64 + k];
                    v1 = p[k + 1] * p[64 + k + 1];
                } else {                                  // p110 = sum_i P1l*P1r
                    int r = k - 64;
                    const float* p = &sP1[t * SP1F];
                    v0 = p[r] * p[64 + r] + p[128 + r] * p[192 + r]
                       + p[256 + r] * p[320 + r];
                    v1 = p[r + 1] * p[65 + r] + p[129 + r] * p[193 + r]
                       + p[257 + r] * p[321 + r];
                }
                uint32_t h, l; split_pair(v0, v1, h, l);
                aH0[t * SAU + kp] = h;
                aL0[t * SAU + kp] = l;
            }
            CP_COMMIT_WAIT();
            __syncthreads();
            gemm_chunk_multi<1>(acc, aBase, wH, wL, mrow0, nb, lane);
        }
#pragma unroll
        for (int nt = 0; nt < 4; ++nt) {
            int col = nb + nt * 8 + 2 * qd;
            float2 b = *(const float2*)&b0o[col];
            *(float2*)&out0[(tokbase + mrow0 + grp) * 128 + col] =
                make_float2(acc[0][nt][0] + b.x, acc[0][nt][1] + b.y);
            *(float2*)&out0[(tokbase + mrow0 + grp + 8) * 128 + col] =
                make_float2(acc[0][nt][2] + b.x, acc[0][nt][3] + b.y);
        }
    }

    // ==== out1_i = [q011|q101|q111]_i @ W1o^T  (one W chunk -> all 3 i) ====
    {
        float acc3[3][4][4];
#pragma unroll
        for (int i = 0; i < 3; ++i) ZERO4(acc3[i]);
        for (int cc = 0; cc < 6; ++cc) {
            __syncthreads();
            stage_W_cp(12 + cc, wH, wL, tid);
            const int cb = cc * 32;
#pragma unroll
            for (int i = 0; i < 3; ++i) {
                const int i1 = (i + 1 < 3) ? i + 1 : i - 2;
                const int i2 = (i + 2 < 3) ? i + 2 : i - 1;
                uint32_t* aH = aBase + i * 1280;
                uint32_t* aL = aH + 640;
#pragma unroll
                for (int it = 0; it < 2; ++it) {
                    int e  = tid + it * THREADS;
                    int kp = (e & 3) | (((e >> 5) & 3) << 2);
                    int t  = ((e >> 2) & 7) | ((e >> 7) << 3);
                    int k  = cb + 2 * kp;
                    const float* p  = &sP1[t * SP1F];
                    const float* p0 = &sP0[t * SP0F];
                    float v0, v1;
                    if (cb < 64) {                        // q011 = P0l * P1r_i
                        v0 = p0[k] * p[i * 128 + 64 + k];
                        v1 = p0[k + 1] * p[i * 128 + 65 + k];
                    } else if (cb < 128) {                // q101 = P1l_i * P0r
                        int r = k - 64;
                        v0 = p[i * 128 + r] * p0[64 + r];
                        v1 = p[i * 128 + r + 1] * p0[65 + r];
                    } else {                              // q111 = cross_i
                        int r = k - 128;
                        v0 = p[i1 * 128 + r] * p[i2 * 128 + 64 + r]
                           - p[i2 * 128 + r] * p[i1 * 128 + 64 + r];
                        v1 = p[i1 * 128 + r + 1] * p[i2 * 128 + 65 + r]
                           - p[i2 * 128 + r + 1] * p[i1 * 128 + 65 + r];
                    }
                    uint32_t h, l; split_pair(v0, v1, h, l);
                    aH[t * SAU + kp] = h;
                    aL[t * SAU + kp] = l;
                }
            }
            CP_COMMIT_WAIT();
            __syncthreads();
            gemm_chunk_multi<3>(acc3, aBase, wH, wL, mrow0, nb, lane);
        }
#pragma unroll
        for (int i = 0; i < 3; ++i)
#pragma unroll
            for (int nt = 0; nt < 4; ++nt) {
                int col = nb + nt * 8 + 2 * qd;
                *(float2*)&out1[(tokbase + mrow0 + grp) * 384 + i * 128 + col] =
                    make_float2(acc3[i][nt][0], acc3[i][nt][1]);
                *(float2*)&out1[(tokbase + mrow0 + grp + 8) * 384 + i * 128 + col] =
                    make_float2(acc3[i][nt][2], acc3[i][nt][3]);
            }
    }
}

extern "C" void kernel_launch(void* const* d_in, const int* in_sizes, int n_in,
                              void* d_out, int out_size) {
    const float* z0  = (const float*)d_in[0];
    const float* z1  = (const float*)d_in[1];
    const float* W0l = (const float*)d_in[2];
    const float* b0l = (const float*)d_in[3];
    const float* W0r = (const float*)d_in[4];
    const float* b0r = (const float*)d_in[5];
    const float* W1l = (const float*)d_in[6];
    const float* W1r = (const float*)d_in[7];
    const float* W0o = (const float*)d_in[8];
    const float* b0o = (const float*)d_in[9];
    const float* W1o = (const float*)d_in[10];

    const int BN = in_sizes[0] / 128;            // 65536 tokens
    float* out0 = (float*)d_out;
    float* out1 = (float*)d_out + (long)BN * 128;

    prep_w_kernel<<<144, 256>>>(W0l, W0r, W1l, W1r, W0o, W1o);

    cudaFuncSetAttribute(etp_bf16_kernel,
                         cudaFuncAttributeMaxDynamicSharedMemorySize, SMEM_BYTES);

    dim3 grid(BN / TOK);    // 2048
    dim3 block(THREADS);
    etp_bf16_kernel<<<grid, block, SMEM_BYTES>>>(z0, z1, b0l, b0r, b0o,
                                                 out0, out1);
}

// round 14
// speedup vs baseline: 3.3062x; 1.0089x over previous
#include <cuda_runtime.h>
#include <cuda_bf16.h>
#include <cstdint>

// ============================================================================
// ElementwiseTensorProducts — mma.sync.m16n8k16 bf16, 2-way split (hh+hl+lh).
//
// R14 changes vs R13 (225us):
//  * A fragments loaded via ldmatrix.x4 (1 LDSM fills 4 frag regs) instead of
//    8 scalar LDS: 48->12 frag-load instructions per NI=3 chunk-warp, shorter
//    scoreboard chains ahead of the MMAs. Bank-conflict-free on SAU=20
//    (row starts 20t mod 32 all distinct; each 8x8 fetch covers all 32 banks).
// Carried: weights pre-split once to __device__ scratch (prep kernel);
// W staging via cp.async.cg; W frags hoisted across the 3-irrep loop;
// register prefetch of gmem A chunks one chunk ahead (cross-phase too).
// Per block: 32 tokens, 8 warps (2 m16-tiles x 4 n32-quarters), 2 CTAs/SM.
// ============================================================================

#define THREADS 256
#define TOK     32
#define SAU     20     // A tile stride (u32 pairs)
#define SWN     136    // W tile stride (u32 pairs): frag banks 8*qd+grp distinct
#define SP0F    140    // P0 stride (floats)
#define SP1F    396    // P1 stride (floats)

// smem byte offsets
#define OFF_A   0          // 3 x (hi 2560 + lo 2560) = 15360
#define OFF_WH  15360      // 16*136*4 = 8704
#define OFF_WL  24064
#define OFF_P0  32768      // 32*140*4 = 17920
#define OFF_P1  50688      // 32*396*4 = 50688
#define SMEM_BYTES 101376

#define WTILE_U32 2176     // 16*136
__device__ __align__(16) uint32_t g_wh[18 * WTILE_U32];
__device__ __align__(16) uint32_t g_wl[18 * WTILE_U32];

__device__ __forceinline__ uint32_t pack2(float v0, float v1) {
    __nv_bfloat162 p = __floats2bfloat162_rn(v0, v1);   // v0 -> low half
    return *(uint32_t*)&p;
}

__device__ __forceinline__ void split_pair(float v0, float v1,
                                           uint32_t& h, uint32_t& l) {
    h = pack2(v0, v1);
    float h0 = __uint_as_float(h << 16);
    float h1 = __uint_as_float(h & 0xffff0000u);
    l = pack2(v0 - h0, v1 - h1);
}

// ---------------- prep kernel: split all 18 W chunk-tiles once ----------------
// tile 0-3: [W0l|W0r] k-slices; 4-7: [W1l|W1r]; 8-11: W0o; 12-17: W1o.
__global__ void prep_w_kernel(const float* __restrict__ W0l,
                              const float* __restrict__ W0r,
                              const float* __restrict__ W1l,
                              const float* __restrict__ W1r,
                              const float* __restrict__ W0o,
                              const float* __restrict__ W1o) {
    int e = blockIdx.x * blockDim.x + threadIdx.x;   // 0..36863
    int n    = e & 127;
    int kp   = (e >> 7) & 15;
    int tile = e >> 11;
    const float* src;
    int kb;
    if (tile < 4)       { kb = tile * 32;        src = (n < 64) ? W0l + n * 128 : W0r + (n - 64) * 128; }
    else if (tile < 8)  { kb = (tile - 4) * 32;  src = (n < 64) ? W1l + n * 128 : W1r + (n - 64) * 128; }
    else if (tile < 12) { kb = (tile - 8) * 32;  src = W0o + n * 128; }
    else                { kb = (tile - 12) * 32; src = W1o + n * 192; }
    float2 v = *(const float2*)(src + kb + 2 * kp);
    uint32_t h, l; split_pair(v.x, v.y, h, l);
    g_wh[tile * WTILE_U32 + kp * 136 + n] = h;
    g_wl[tile * WTILE_U32 + kp * 136 + n] = l;
}

// ---------------- main kernel helpers ----------------
__device__ __forceinline__ void mma16(float (&c)[4], const uint32_t (&a)[4],
                                      uint32_t b0, uint32_t b1) {
    asm volatile(
        "mma.sync.aligned.m16n8k16.row.col.f32.bf16.bf16.f32 "
        "{%0,%1,%2,%3}, {%4,%5,%6,%7}, {%8,%9}, {%0,%1,%2,%3};"
        : "+f"(c[0]), "+f"(c[1]), "+f"(c[2]), "+f"(c[3])
        : "r"(a[0]), "r"(a[1]), "r"(a[2]), "r"(a[3]), "r"(b0), "r"(b1));
}

__device__ __forceinline__ void ldsm_x4(uint32_t (&r)[4], const uint32_t* p) {
    uint32_t a = (uint32_t)__cvta_generic_to_shared(p);
    asm volatile("ldmatrix.sync.aligned.m8n8.x4.shared.b16 {%0,%1,%2,%3}, [%4];"
                 : "=r"(r[0]), "=r"(r[1]), "=r"(r[2]), "=r"(r[3]) : "r"(a));
}

// NI irreps per staged W chunk. A frags via ldmatrix.x4; W frags loaded from
// smem exactly once per chunk and reused across the NI irreps.
template <int NI>
__device__ __forceinline__ void gemm_chunk_multi(float (&acc)[NI][4][4],
        const uint32_t* __restrict__ aBase,   // per-i stride 1280; lo at +640
        const uint32_t* __restrict__ wH, const uint32_t* __restrict__ wL,
        int mrow0, int nb, int lane) {
    const int grp = lane >> 2, qd = lane & 3;
    // ldmatrix lane -> (token, kp-group) mapping for the 4 8x8 matrices
    const int ltok = mrow0 + (lane & 7) + ((lane >> 3) & 1) * 8;
    const int lkp  = (lane >> 4) * 4;
#pragma unroll
    for (int ks = 0; ks < 2; ++ks) {
        uint32_t ah[NI][4], al[NI][4];
#pragma unroll
        for (int i = 0; i < NI; ++i) {
            const uint32_t* ph = aBase + i * 1280 + ltok * SAU + 8 * ks + lkp;
            ldsm_x4(ah[i], ph);
            ldsm_x4(al[i], ph + 640);
        }
#pragma unroll
        for (int nt = 0; nt < 4; ++nt) {
            const uint32_t* pwh = wH + (8 * ks + qd) * SWN + nb + grp + 8 * nt;
            const uint32_t* pwl = wL + (8 * ks + qd) * SWN + nb + grp + 8 * nt;
            uint32_t bh0 = pwh[0], bh1 = pwh[4 * SWN];
            uint32_t bl0 = pwl[0], bl1 = pwl[4 * SWN];
#pragma unroll
            for (int i = 0; i < NI; ++i) {
                mma16(acc[i][nt], ah[i], bh0, bh1);
                mma16(acc[i][nt], ah[i], bl0, bl1);
                mma16(acc[i][nt], al[i], bh0, bh1);
            }
        }
    }
}

// Stage pre-split W tile via cp.async (16 rows x 32 uint4 used per buffer).
__device__ __forceinline__ void stage_W_cp(int tile,
                                           uint32_t* __restrict__ wH,
                                           uint32_t* __restrict__ wL, int tid) {
    const uint4* sh = (const uint4*)(g_wh + tile * WTILE_U32);
    const uint4* sl = (const uint4*)(g_wl + tile * WTILE_U32);
#pragma unroll
    for (int it = 0; it < 2; ++it) {
        int idx = tid + it * THREADS;        // 0..511 : row 0..15, quad 0..31
        int row = idx >> 5, q = idx & 31;
        uint32_t dh = (uint32_t)__cvta_generic_to_shared((uint4*)wH + row * 34 + q);
        uint32_t dl = (uint32_t)__cvta_generic_to_shared((uint4*)wL + row * 34 + q);
        asm volatile("cp.async.cg.shared.global [%0], [%1], 16;"
                     :: "r"(dh), "l"(sh + row * 34 + q));
        asm volatile("cp.async.cg.shared.global [%0], [%1], 16;"
                     :: "r"(dl), "l"(sl + row * 34 + q));
    }
}

#define CP_COMMIT_WAIT() do {                                     \
    asm volatile("cp.async.commit_group;" ::: "memory");          \
    asm volatile("cp.async.wait_group 0;" ::: "memory");          \
} while (0)

// -------- A staging split into prefetch (LDG -> regs) + commit (split+STS) ---
__device__ __forceinline__ void prefetch_A(const float* __restrict__ src, int ld,
                                           float2 (&pre)[2], int tid) {
#pragma unroll
    for (int it = 0; it < 2; ++it) {
        int e  = tid + it * THREADS;                 // 0..511
        int kp = (e & 3) | (((e >> 5) & 3) << 2);    // 0..15
        int t  = ((e >> 2) & 7) | ((e >> 7) << 3);   // 0..31
        pre[it] = *(const float2*)(src + (long)t * ld + 2 * kp);
    }
}

__device__ __forceinline__ void commit_A(const float2 (&pre)[2],
                                         uint32_t* __restrict__ aH,
                                         uint32_t* __restrict__ aL, int tid) {
#pragma unroll
    for (int it = 0; it < 2; ++it) {
        int e  = tid + it * THREADS;
        int kp = (e & 3) | (((e >> 5) & 3) << 2);
        int t  = ((e >> 2) & 7) | ((e >> 7) << 3);
        uint32_t h, l; split_pair(pre[it].x, pre[it].y, h, l);
        aH[t * SAU + kp] = h;
        aL[t * SAU + kp] = l;
    }
}

#define ZERO4(acc) do {                                      \
    _Pragma("unroll") for (int _n = 0; _n < 4; ++_n)         \
    _Pragma("unroll") for (int _m = 0; _m < 4; ++_m)         \
        (acc)[_n][_m] = 0.f;                                 \
} while (0)

__global__ __launch_bounds__(THREADS, 2)
void etp_bf16_kernel(const float* __restrict__ z0, const float* __restrict__ z1,
                     const float* __restrict__ b0l, const float* __restrict__ b0r,
                     const float* __restrict__ b0o,
                     float* __restrict__ out0, float* __restrict__ out1) {
    extern __shared__ char smem[];
    uint32_t* aBase = (uint32_t*)(smem + OFF_A);     // 3 x (hi 640 | lo 640) u32
    uint32_t* wH    = (uint32_t*)(smem + OFF_WH);
    uint32_t* wL    = (uint32_t*)(smem + OFF_WL);
    float*    sP0   = (float*)(smem + OFF_P0);
    float*    sP1   = (float*)(smem + OFF_P1);

    const int tid  = threadIdx.x;
    const int lane = tid & 31;
    const int warp = tid >> 5;
    const int grp  = lane >> 2, qd = lane & 3;
    const int mrow0 = (warp & 1) * 16;
    const int nb    = (warp >> 1) * 32;
    const long tokbase = (long)blockIdx.x * TOK;

    uint32_t* aH0 = aBase;
    uint32_t* aL0 = aBase + 640;

    float2 pre1[3][2];   // proj1 prefetch registers (live from end of proj0)

    // ================= proj0: P0 = z0 @ [W0l|W0r]^T + bias =================
    {
        float acc[1][4][4]; ZERO4(acc[0]);
        float2 pre0[2];
        prefetch_A(z0 + tokbase * 128, 128, pre0, tid);
        for (int c = 0; c < 4; ++c) {
            __syncthreads();
            stage_W_cp(c, wH, wL, tid);
            commit_A(pre0, aH0, aL0, tid);
            if (c < 3) {
                prefetch_A(z0 + tokbase * 128 + (c + 1) * 32, 128, pre0, tid);
            } else {
                // cross-phase: issue proj1 chunk-0 loads now
#pragma unroll
                for (int i = 0; i < 3; ++i)
                    prefetch_A(z1 + tokbase * 384 + i * 128, 384, pre1[i], tid);
            }
            CP_COMMIT_WAIT();
            __syncthreads();
            gemm_chunk_multi<1>(acc, aBase, wH, wL, mrow0, nb, lane);
        }
#pragma unroll
        for (int nt = 0; nt < 4; ++nt) {
            int col = nb + nt * 8 + 2 * qd;
            float bx = (col < 64) ? b0l[col] : b0r[col - 64];
            float by = (col < 64) ? b0l[col + 1] : b0r[col - 63];
            *(float2*)&sP0[(mrow0 + grp) * SP0F + col] =
                make_float2(acc[0][nt][0] + bx, acc[0][nt][1] + by);
            *(float2*)&sP0[(mrow0 + grp + 8) * SP0F + col] =
                make_float2(acc[0][nt][2] + bx, acc[0][nt][3] + by);
        }
    }

    // ====== proj1: P1_i = z1_i @ [W1l|W1r]^T  (one W chunk -> all 3 i) ======
    {
        float acc3[3][4][4];
#pragma unroll
        for (int i = 0; i < 3; ++i) ZERO4(acc3[i]);
        for (int c = 0; c < 4; ++c) {
            __syncthreads();
            stage_W_cp(4 + c, wH, wL, tid);
#pragma unroll
            for (int i = 0; i < 3; ++i)
                commit_A(pre1[i], aBase + i * 1280, aBase + i * 1280 + 640, tid);
            if (c < 3) {
#pragma unroll
                for (int i = 0; i < 3; ++i)
                    prefetch_A(z1 + tokbase * 384 + i * 128 + (c + 1) * 32, 384,
                               pre1[i], tid);
            }
            CP_COMMIT_WAIT();
            __syncthreads();
            gemm_chunk_multi<3>(acc3, aBase, wH, wL, mrow0, nb, lane);
        }
#pragma unroll
        for (int i = 0; i < 3; ++i)
#pragma unroll
            for (int nt = 0; nt < 4; ++nt) {
                int col = i * 128 + nb + nt * 8 + 2 * qd;
                *(float2*)&sP1[(mrow0 + grp) * SP1F + col] =
                    make_float2(acc3[i][nt][0], acc3[i][nt][1]);
                *(float2*)&sP1[(mrow0 + grp + 8) * SP1F + col] =
                    make_float2(acc3[i][nt][2], acc3[i][nt][3]);
            }
    }

    // ================= out0 = [p00 | p110] @ W0o^T + b0o =================
    {
        float acc[1][4][4]; ZERO4(acc[0]);
        for (int c = 0; c < 4; ++c) {
            __syncthreads();
            stage_W_cp(8 + c, wH, wL, tid);
            const int cb = c * 32;
#pragma unroll
            for (int it = 0; it < 2; ++it) {
                int e  = tid + it * THREADS;
                int kp = (e & 3) | (((e >> 5) & 3) << 2);
                int t  = ((e >> 2) & 7) | ((e >> 7) << 3);
                int k  = cb + 2 * kp;
                float v0, v1;
                if (cb < 64) {                            // p00 = P0l * P0r
                    const float* p = &sP0[t * SP0F];
                    v0 = p[k] * p[64 + k];
                    v1 = p[k + 1] * p[64 + k + 1];
                } else {                                  // p110 = sum_i P1l*P1r
                    int r = k - 64;
                    const float* p = &sP1[t * SP1F];
                    v0 = p[r] * p[64 + r] + p[128 + r] * p[192 + r]
                       + p[256 + r] * p[320 + r];
                    v1 = p[r + 1] * p[65 + r] + p[129 + r] * p[193 + r]
                       + p[257 + r] * p[321 + r];
                }
                uint32_t h, l; split_pair(v0, v1, h, l);
                aH0[t * SAU + kp] = h;
                aL0[t * SAU + kp] = l;
            }
            CP_COMMIT_WAIT();
            __syncthreads();
            gemm_chunk_multi<1>(acc, aBase, wH, wL, mrow0, nb, lane);
        }
#pragma unroll
        for (int nt = 0; nt < 4; ++nt) {
            int col = nb + nt * 8 + 2 * qd;
            float2 b = *(const float2*)&b0o[col];
            *(float2*)&out0[(tokbase + mrow0 + grp) * 128 + col] =
                make_float2(acc[0][nt][0] + b.x, acc[0][nt][1] + b.y);
            *(float2*)&out0[(tokbase + mrow0 + grp + 8) * 128 + col] =
                make_float2(acc[0][nt][2] + b.x, acc[0][nt][3] + b.y);
        }
    }

    // ==== out1_i = [q011|q101|q111]_i @ W1o^T  (one W chunk -> all 3 i) ====
    {
        float acc3[3][4][4];
#pragma unroll
        for (int i = 0; i < 3; ++i) ZERO4(acc3[i]);
        for (int cc = 0; cc < 6; ++cc) {
            __syncthreads();
            stage_W_cp(12 + cc, wH, wL, tid);
            const int cb = cc * 32;
#pragma unroll
            for (int i = 0; i < 3; ++i) {
                const int i1 = (i + 1 < 3) ? i + 1 : i - 2;
                const int i2 = (i + 2 < 3) ? i + 2 : i - 1;
                uint32_t* aH = aBase + i * 1280;
                uint32_t* aL = aH + 640;
#pragma unroll
                for (int it = 0; it < 2; ++it) {
                    int e  = tid + it * THREADS;
                    int kp = (e & 3) | (((e >> 5) & 3) << 2);
                    int t  = ((e >> 2) & 7) | ((e >> 7) << 3);
                    int k  = cb + 2 * kp;
                    const float* p  = &sP1[t * SP1F];
                    const float* p0 = &sP0[t * SP0F];
                    float v0, v1;
                    if (cb < 64) {                        // q011 = P0l * P1r_i
                        v0 = p0[k] * p[i * 128 + 64 + k];
                        v1 = p0[k + 1] * p[i * 128 + 65 + k];
                    } else if (cb < 128) {                // q101 = P1l_i * P0r
                        int r = k - 64;
                        v0 = p[i * 128 + r] * p0[64 + r];
                        v1 = p[i * 128 + r + 1] * p0[65 + r];
                    } else {                              // q111 = cross_i
                        int r = k - 128;
                        v0 = p[i1 * 128 + r] * p[i2 * 128 + 64 + r]
                           - p[i2 * 128 + r] * p[i1 * 128 + 64 + r];
                        v1 = p[i1 * 128 + r + 1] * p[i2 * 128 + 65 + r]
                           - p[i2 * 128 + r + 1] * p[i1 * 128 + 65 + r];
                    }
                    uint32_t h, l; split_pair(v0, v1, h, l);
                    aH[t * SAU + kp] = h;
                    aL[t * SAU + kp] = l;
                }
            }
            CP_COMMIT_WAIT();
            __syncthreads();
            gemm_chunk_multi<3>(acc3, aBase, wH, wL, mrow0, nb, lane);
        }
#pragma unroll
        for (int i = 0; i < 3; ++i)
#pragma unroll
            for (int nt = 0; nt < 4; ++nt) {
                int col = nb + nt * 8 + 2 * qd;
                *(float2*)&out1[(tokbase + mrow0 + grp) * 384 + i * 128 + col] =
                    make_float2(acc3[i][nt][0], acc3[i][nt][1]);
                *(float2*)&out1[(tokbase + mrow0 + grp + 8) * 384 + i * 128 + col] =
                    make_float2(acc3[i][nt][2], acc3[i][nt][3]);
            }
    }
}

extern "C" void kernel_launch(void* const* d_in, const int* in_sizes, int n_in,
                              void* d_out, int out_size) {
    const float* z0  = (const float*)d_in[0];
    const float* z1  = (const float*)d_in[1];
    const float* W0l = (const float*)d_in[2];
    const float* b0l = (const float*)d_in[3];
    const float* W0r = (const float*)d_in[4];
    const float* b0r = (const float*)d_in[5];
    const float* W1l = (const float*)d_in[6];
    const float* W1r = (const float*)d_in[7];
    const float* W0o = (const float*)d_in[8];
    const float* b0o = (const float*)d_in[9];
    const float* W1o = (const float*)d_in[10];

    const int BN = in_sizes[0] / 128;            // 65536 tokens
    float* out0 = (float*)d_out;
    float* out1 = (float*)d_out + (long)BN * 128;

    prep_w_kernel<<<144, 256>>>(W0l, W0r, W1l, W1r, W0o, W1o);

    cudaFuncSetAttribute(etp_bf16_kernel,
                         cudaFuncAttributeMaxDynamicSharedMemorySize, SMEM_BYTES);

    dim3 grid(BN / TOK);    // 2048
    dim3 block(THREADS);
    etp_bf16_kernel<<<grid, block, SMEM_BYTES>>>(z0, z1, b0l, b0r, b0o,
                                                 out0, out1);
}